// round 1
// baseline (speedup 1.0000x reference)
#include <cuda_runtime.h>
#include <cuda_bf16.h>
#include <math.h>

// Problem constants
#define B_  8
#define S_  1024
#define H_  16
#define HD_ 64
#define D_  1024
#define M_  (B_ * S_)       // 8192
#define NINF_ (-10000.0f)

// Scratch (no allocations allowed -> __device__ globals)
#define QKV_ELEMS (B_ * H_ * S_ * HD_)   // 8,388,608
__device__ float g_Q[QKV_ELEMS];
__device__ float g_K[QKV_ELEMS];
__device__ float g_V[QKV_ELEMS];
__device__ float g_ctx[M_ * D_];
__device__ float g_y[M_ * D_];

// ---------------------------------------------------------------------------
// SGEMM: C[M,N] = A[M,K] @ W[K,N] + bias (+ optional residual), fp32
// 128x128 block tile, BK=16, 256 threads, 8x8 per-thread micro tile.
// heads_mode=1: scatter output into [B,H,S,HD] layout (for Q/K/V).
// heads_mode=0: flat row-major [M,N] with residual add (for out-proj).
// ---------------------------------------------------------------------------
#define BKD 16
#define AST 132   // padded stride for transposed A tile (mod-4 aligned)

__global__ __launch_bounds__(256) void sgemm_kernel(
    const float* __restrict__ A, const float* __restrict__ W,
    const float* __restrict__ bias, const float* __restrict__ resid,
    float* __restrict__ Cout, int K, int N, int heads_mode)
{
    __shared__ float As[BKD][AST];   // [k][m] transposed
    __shared__ float Bs[BKD][128];   // [k][n]

    const int tid = threadIdx.x;
    const int ty = tid >> 4;       // 0..15 -> owns 8 m-rows
    const int tx = tid & 15;       // 0..15 -> owns 8 n-cols
    const int bm = blockIdx.y * 128;
    const int bn = blockIdx.x * 128;

    const float* Aptr = A + (size_t)bm * K;
    const float* Wptr = W + bn;

    float acc[8][8];
#pragma unroll
    for (int i = 0; i < 8; i++)
#pragma unroll
        for (int j = 0; j < 8; j++) acc[i][j] = 0.f;

    for (int k0 = 0; k0 < K; k0 += BKD) {
        // Load A tile 128x16 -> transposed smem
#pragma unroll
        for (int it = 0; it < 2; it++) {
            int l = it * 256 + tid;          // 0..511
            int r = l >> 2;                  // 0..127
            int c = (l & 3) << 2;            // 0,4,8,12
            float4 v = *(const float4*)(Aptr + (size_t)r * K + k0 + c);
            As[c + 0][r] = v.x; As[c + 1][r] = v.y;
            As[c + 2][r] = v.z; As[c + 3][r] = v.w;
        }
        // Load W tile 16x128 -> natural smem
#pragma unroll
        for (int it = 0; it < 2; it++) {
            int l = it * 256 + tid;
            int r = l >> 5;                  // 0..15
            int c = (l & 31) << 2;           // 0..124
            *(float4*)&Bs[r][c] = *(const float4*)(Wptr + (size_t)(k0 + r) * N + c);
        }
        __syncthreads();

#pragma unroll
        for (int d = 0; d < BKD; d++) {
            float a[8], b[8];
            *(float4*)&a[0] = *(const float4*)&As[d][ty * 8];
            *(float4*)&a[4] = *(const float4*)&As[d][ty * 8 + 4];
            *(float4*)&b[0] = *(const float4*)&Bs[d][tx * 8];
            *(float4*)&b[4] = *(const float4*)&Bs[d][tx * 8 + 4];
#pragma unroll
            for (int i = 0; i < 8; i++)
#pragma unroll
                for (int j = 0; j < 8; j++)
                    acc[i][j] += a[i] * b[j];
        }
        __syncthreads();
    }

    // Epilogue
    const int n0 = bn + tx * 8;
    float bi[8];
#pragma unroll
    for (int j = 0; j < 8; j++) bi[j] = bias[n0 + j];

    if (heads_mode) {
#pragma unroll
        for (int i = 0; i < 8; i++) {
            int m = bm + ty * 8 + i;
            int bidx = m >> 10, srow = m & 1023;
            int h = n0 >> 6, hd = n0 & 63;
            float* outp = Cout + (((size_t)(bidx * H_ + h)) << 16) + srow * HD_ + hd;
            float4 o0, o1;
            o0.x = acc[i][0] + bi[0]; o0.y = acc[i][1] + bi[1];
            o0.z = acc[i][2] + bi[2]; o0.w = acc[i][3] + bi[3];
            o1.x = acc[i][4] + bi[4]; o1.y = acc[i][5] + bi[5];
            o1.z = acc[i][6] + bi[6]; o1.w = acc[i][7] + bi[7];
            *(float4*)outp = o0;
            *(float4*)(outp + 4) = o1;
        }
    } else {
#pragma unroll
        for (int i = 0; i < 8; i++) {
            size_t off = (size_t)(bm + ty * 8 + i) * N + n0;
            float4 r0 = *(const float4*)(resid + off);
            float4 r1 = *(const float4*)(resid + off + 4);
            float4 o0, o1;
            o0.x = acc[i][0] + bi[0] + r0.x; o0.y = acc[i][1] + bi[1] + r0.y;
            o0.z = acc[i][2] + bi[2] + r0.z; o0.w = acc[i][3] + bi[3] + r0.w;
            o1.x = acc[i][4] + bi[4] + r1.x; o1.y = acc[i][5] + bi[5] + r1.y;
            o1.z = acc[i][6] + bi[6] + r1.z; o1.w = acc[i][7] + bi[7] + r1.w;
            *(float4*)(Cout + off) = o0;
            *(float4*)(Cout + off + 4) = o1;
        }
    }
}

// ---------------------------------------------------------------------------
// Attention: per block = one (b,h) and one 128-row query tile.
// Flash-style online softmax over 8 key tiles of 128.
// 256 threads: (ty,tx) 16x16; ty owns 8 q-rows, tx owns 8 k-cols (scores)
// and 4 v-cols (PV).
// ---------------------------------------------------------------------------
#define QT_F (64 * 132)
#define KT_F (64 * 132)
#define VS_F (128 * 64)
#define PS_F (128 * 132)
#define MS_F 128
#define ATTN_SMEM_BYTES ((QT_F + KT_F + VS_F + PS_F + MS_F) * 4)

__global__ __launch_bounds__(256, 1) void attn_kernel(
    const float* __restrict__ Q, const float* __restrict__ K,
    const float* __restrict__ V, const int* __restrict__ mask,
    float* __restrict__ ctx)
{
    extern __shared__ float sm[];
    float* Qt = sm;              // [64 d][132 q]
    float* Kt = Qt + QT_F;       // [64 d][132 k]
    float* Vs = Kt + KT_F;       // [128 k][64 v]
    float* Ps = Vs + VS_F;       // [128 q][132 k]
    float* Ms = Ps + PS_F;       // [128] mask addend

    const int tid = threadIdx.x;
    const int ty = tid >> 4, tx = tid & 15;
    const int bh = blockIdx.y;          // b*H + h
    const int b = bh >> 4;
    const int h = bh & 15;
    const int q0 = blockIdx.x * 128;

    const float* Qp = Q + (((size_t)bh) << 16) + (size_t)q0 * HD_;
    const float* Kp = K + (((size_t)bh) << 16);
    const float* Vp = V + (((size_t)bh) << 16);
    const int* mp = mask + b * S_;

    // Load Q tile transposed: Qt[d][q]
#pragma unroll
    for (int it = 0; it < 8; it++) {
        int l = it * 256 + tid;           // 0..2047
        int r = l >> 4;                   // q row 0..127
        int c = (l & 15) << 2;            // d 0..60
        float4 v = *(const float4*)(Qp + (size_t)r * HD_ + c);
        Qt[(c + 0) * 132 + r] = v.x; Qt[(c + 1) * 132 + r] = v.y;
        Qt[(c + 2) * 132 + r] = v.z; Qt[(c + 3) * 132 + r] = v.w;
    }

    float m[8], lsum[8], c4a[8][4];
#pragma unroll
    for (int i = 0; i < 8; i++) {
        m[i] = -1e30f; lsum[i] = 0.f;
        c4a[i][0] = c4a[i][1] = c4a[i][2] = c4a[i][3] = 0.f;
    }

    for (int k0 = 0; k0 < S_; k0 += 128) {
        // Load K (transposed) and V (natural) tiles + mask
#pragma unroll
        for (int it = 0; it < 8; it++) {
            int l = it * 256 + tid;
            int r = l >> 4;
            int c = (l & 15) << 2;
            float4 kv = *(const float4*)(Kp + (size_t)(k0 + r) * HD_ + c);
            Kt[(c + 0) * 132 + r] = kv.x; Kt[(c + 1) * 132 + r] = kv.y;
            Kt[(c + 2) * 132 + r] = kv.z; Kt[(c + 3) * 132 + r] = kv.w;
            float4 vv = *(const float4*)(Vp + (size_t)(k0 + r) * HD_ + c);
            *(float4*)&Vs[r * 64 + c] = vv;
        }
        if (tid < 128) Ms[tid] = NINF_ * (float)mp[k0 + tid];
        __syncthreads();

        // Scores: s[8][8] = Q_tile @ K_tile^T
        float s[8][8];
#pragma unroll
        for (int i = 0; i < 8; i++)
#pragma unroll
            for (int j = 0; j < 8; j++) s[i][j] = 0.f;

#pragma unroll
        for (int d = 0; d < HD_; d++) {
            float a[8], bb[8];
            *(float4*)&a[0]  = *(const float4*)&Qt[d * 132 + ty * 8];
            *(float4*)&a[4]  = *(const float4*)&Qt[d * 132 + ty * 8 + 4];
            *(float4*)&bb[0] = *(const float4*)&Kt[d * 132 + tx * 8];
            *(float4*)&bb[4] = *(const float4*)&Kt[d * 132 + tx * 8 + 4];
#pragma unroll
            for (int i = 0; i < 8; i++)
#pragma unroll
                for (int j = 0; j < 8; j++)
                    s[i][j] += a[i] * bb[j];
        }

        // Mask + online softmax (per q-row; reduce across 16 tx threads)
#pragma unroll
        for (int i = 0; i < 8; i++) {
            float mx = -1e30f;
#pragma unroll
            for (int j = 0; j < 8; j++) {
                s[i][j] = s[i][j] * 0.125f + Ms[tx * 8 + j];
                mx = fmaxf(mx, s[i][j]);
            }
            mx = fmaxf(mx, __shfl_xor_sync(0xffffffffu, mx, 1));
            mx = fmaxf(mx, __shfl_xor_sync(0xffffffffu, mx, 2));
            mx = fmaxf(mx, __shfl_xor_sync(0xffffffffu, mx, 4));
            mx = fmaxf(mx, __shfl_xor_sync(0xffffffffu, mx, 8));
            float nm = fmaxf(m[i], mx);
            float corr = __expf(m[i] - nm);
            m[i] = nm;
            float pv[8];
            float rs = 0.f;
#pragma unroll
            for (int j = 0; j < 8; j++) { pv[j] = __expf(s[i][j] - nm); rs += pv[j]; }
            rs += __shfl_xor_sync(0xffffffffu, rs, 1);
            rs += __shfl_xor_sync(0xffffffffu, rs, 2);
            rs += __shfl_xor_sync(0xffffffffu, rs, 4);
            rs += __shfl_xor_sync(0xffffffffu, rs, 8);
            lsum[i] = lsum[i] * corr + rs;
            c4a[i][0] *= corr; c4a[i][1] *= corr;
            c4a[i][2] *= corr; c4a[i][3] *= corr;
            float* pr = &Ps[(ty * 8 + i) * 132 + tx * 8];
            *(float4*)pr       = make_float4(pv[0], pv[1], pv[2], pv[3]);
            *(float4*)(pr + 4) = make_float4(pv[4], pv[5], pv[6], pv[7]);
        }
        __syncthreads();

        // ctx += P @ V   (thread: 8 q-rows x 4 v-cols)
#pragma unroll 4
        for (int kk = 0; kk < 128; kk++) {
            float4 vv = *(const float4*)&Vs[kk * 64 + tx * 4];
#pragma unroll
            for (int i = 0; i < 8; i++) {
                float p = Ps[(ty * 8 + i) * 132 + kk];
                c4a[i][0] += p * vv.x; c4a[i][1] += p * vv.y;
                c4a[i][2] += p * vv.z; c4a[i][3] += p * vv.w;
            }
        }
        __syncthreads();
    }

    // Write ctx in [B,S,D] layout
#pragma unroll
    for (int i = 0; i < 8; i++) {
        float inv = 1.0f / lsum[i];
        size_t off = (size_t)(b * S_ + q0 + ty * 8 + i) * D_ + h * HD_ + tx * 4;
        float4 o;
        o.x = c4a[i][0] * inv; o.y = c4a[i][1] * inv;
        o.z = c4a[i][2] * inv; o.w = c4a[i][3] * inv;
        *(float4*)(ctx + off) = o;
    }
}

// ---------------------------------------------------------------------------
// Row LayerNorm over [M, 1024]
// ---------------------------------------------------------------------------
__global__ __launch_bounds__(256) void ln_kernel(
    const float* __restrict__ Y, const float* __restrict__ gamma,
    const float* __restrict__ beta, float* __restrict__ O)
{
    __shared__ float red[16];
    const int row = blockIdx.x;
    const int t = threadIdx.x;
    const float* yr = Y + (size_t)row * D_;
    float4 v = *(const float4*)(yr + t * 4);
    float s  = v.x + v.y + v.z + v.w;
    float sq = v.x * v.x + v.y * v.y + v.z * v.z + v.w * v.w;
#pragma unroll
    for (int o = 16; o; o >>= 1) {
        s  += __shfl_xor_sync(0xffffffffu, s, o);
        sq += __shfl_xor_sync(0xffffffffu, sq, o);
    }
    int w = t >> 5;
    if ((t & 31) == 0) { red[w] = s; red[8 + w] = sq; }
    __syncthreads();
    if (t < 32) {
        s  = (t < 8) ? red[t] : 0.f;
        sq = (t < 8) ? red[8 + t] : 0.f;
#pragma unroll
        for (int o = 4; o; o >>= 1) {
            s  += __shfl_xor_sync(0xffffffffu, s, o);
            sq += __shfl_xor_sync(0xffffffffu, sq, o);
        }
        if (t == 0) { red[0] = s; red[1] = sq; }
    }
    __syncthreads();
    float mu  = red[0] * (1.0f / D_);
    float var = red[1] * (1.0f / D_) - mu * mu;
    float rstd = rsqrtf(var + 1e-6f);
    float4 g  = *(const float4*)(gamma + t * 4);
    float4 be = *(const float4*)(beta + t * 4);
    float4 o;
    o.x = (v.x - mu) * rstd * g.x + be.x;
    o.y = (v.y - mu) * rstd * g.y + be.y;
    o.z = (v.z - mu) * rstd * g.z + be.z;
    o.w = (v.w - mu) * rstd * g.w + be.w;
    *(float4*)(O + (size_t)row * D_ + t * 4) = o;
}

// ---------------------------------------------------------------------------
// Launch
// ---------------------------------------------------------------------------
extern "C" void kernel_launch(void* const* d_in, const int* in_sizes, int n_in,
                              void* d_out, int out_size)
{
    const float* x     = (const float*)d_in[0];
    const int*   mask  = (const int*)d_in[1];
    const float* wq    = (const float*)d_in[2];
    const float* bq    = (const float*)d_in[3];
    const float* wk    = (const float*)d_in[4];
    const float* bk    = (const float*)d_in[5];
    const float* wv    = (const float*)d_in[6];
    const float* bv    = (const float*)d_in[7];
    const float* wo    = (const float*)d_in[8];
    const float* bo    = (const float*)d_in[9];
    const float* gamma = (const float*)d_in[10];
    const float* beta  = (const float*)d_in[11];
    float* out = (float*)d_out;

    float *Qp, *Kp, *Vp, *ctxp, *yp;
    cudaGetSymbolAddress((void**)&Qp, g_Q);
    cudaGetSymbolAddress((void**)&Kp, g_K);
    cudaGetSymbolAddress((void**)&Vp, g_V);
    cudaGetSymbolAddress((void**)&ctxp, g_ctx);
    cudaGetSymbolAddress((void**)&yp, g_y);

    cudaFuncSetAttribute(attn_kernel,
                         cudaFuncAttributeMaxDynamicSharedMemorySize,
                         ATTN_SMEM_BYTES);

    dim3 gGemm(D_ / 128, M_ / 128);   // (8, 64)

    sgemm_kernel<<<gGemm, 256>>>(x, wq, bq, nullptr, Qp, D_, D_, 1);
    sgemm_kernel<<<gGemm, 256>>>(x, wk, bk, nullptr, Kp, D_, D_, 1);
    sgemm_kernel<<<gGemm, 256>>>(x, wv, bv, nullptr, Vp, D_, D_, 1);

    dim3 gAttn(S_ / 128, B_ * H_);    // (8, 128)
    attn_kernel<<<gAttn, 256, ATTN_SMEM_BYTES>>>(Qp, Kp, Vp, mask, ctxp);

    sgemm_kernel<<<gGemm, 256>>>(ctxp, wo, bo, x, yp, D_, D_, 0);

    ln_kernel<<<M_, 256>>>(yp, gamma, beta, out);
}

// round 2
// speedup vs baseline: 4.0533x; 4.0533x over previous
#include <cuda_runtime.h>
#include <cuda_bf16.h>
#include <mma.h>
#include <math.h>

using namespace nvcuda;

#define B_  8
#define S_  1024
#define H_  16
#define HD_ 64
#define D_  1024
#define M_  (B_ * S_)       // 8192
#define NINF_ (-10000.0f)

// ---------------- scratch (no allocs allowed) ----------------
__device__ __nv_bfloat16 g_xb[M_ * D_];
__device__ __nv_bfloat16 g_wqb[D_ * D_];
__device__ __nv_bfloat16 g_wkb[D_ * D_];
__device__ __nv_bfloat16 g_wvb[D_ * D_];
__device__ __nv_bfloat16 g_wob[D_ * D_];
__device__ __nv_bfloat16 g_Qb[M_ * D_];   // [B*H][S][HD]
__device__ __nv_bfloat16 g_Kb[M_ * D_];
__device__ __nv_bfloat16 g_Vb[M_ * D_];
__device__ __nv_bfloat16 g_ctxb[M_ * D_]; // [B*S][D]
__device__ float g_y[M_ * D_];

// ---------------- fp32 -> bf16 conversion ----------------
__global__ __launch_bounds__(256) void f2bf_kernel(
    const float* __restrict__ in, __nv_bfloat16* __restrict__ out, int n)
{
    int i = (blockIdx.x * 256 + threadIdx.x) * 4;
    if (i >= n) return;
    float4 v = *(const float4*)(in + i);
    __nv_bfloat162 a = __floats2bfloat162_rn(v.x, v.y);
    __nv_bfloat162 b = __floats2bfloat162_rn(v.z, v.w);
    *(__nv_bfloat162*)(out + i)     = a;
    *(__nv_bfloat162*)(out + i + 2) = b;
}

// ---------------- cp.async helpers ----------------
__device__ __forceinline__ void cpa16(void* s, const void* g) {
    unsigned sa = (unsigned)__cvta_generic_to_shared(s);
    asm volatile("cp.async.cg.shared.global [%0], [%1], 16;\n" :: "r"(sa), "l"(g));
}
__device__ __forceinline__ void cp_commit() { asm volatile("cp.async.commit_group;\n"); }
__device__ __forceinline__ void cp_wait1()  { asm volatile("cp.async.wait_group 1;\n" ::: "memory"); }

// ---------------------------------------------------------------------------
// bf16 wmma GEMM: C[8192,1024] = A[8192,1024] @ W[1024,1024] (+bias, +resid)
// block 128x128, 8 warps (4x2), warp tile 32x64, BK=32, 2-stage cp.async.
// heads_mode=1 -> write bf16 into [B,H,S,HD]; else fp32 + resid into OutF.
// ---------------------------------------------------------------------------
#define AS_ 40
#define BS_ 136

struct GemmSmem {
    __nv_bfloat16 As[2][128][AS_];
    __nv_bfloat16 Bs[2][32][BS_];
    float scratch[8][16][20];
};

__global__ __launch_bounds__(256, 2) void gemm_bf16_kernel(
    const __nv_bfloat16* __restrict__ A, const __nv_bfloat16* __restrict__ W,
    const float* __restrict__ bias, const float* __restrict__ resid,
    __nv_bfloat16* __restrict__ OutB, float* __restrict__ OutF, int heads_mode)
{
    __shared__ GemmSmem sm;
    const int tid = threadIdx.x;
    const int w = tid >> 5, lane = tid & 31;
    const int wm = w >> 1, wn = w & 1;
    const int bm = blockIdx.y * 128, bn = blockIdx.x * 128;

    wmma::fragment<wmma::accumulator, 16, 16, 16, float> acc[2][4];
#pragma unroll
    for (int i = 0; i < 2; i++)
#pragma unroll
        for (int j = 0; j < 4; j++) wmma::fill_fragment(acc[i][j], 0.0f);

    // prefetch stage 0
    {
        int k0 = 0;
#pragma unroll
        for (int it = 0; it < 2; it++) {
            int l = it * 256 + tid;
            int r = l >> 2, c = (l & 3) * 8;
            cpa16(&sm.As[0][r][c], A + (size_t)(bm + r) * D_ + k0 + c);
            int r2 = l >> 4, c2 = (l & 15) * 8;
            cpa16(&sm.Bs[0][r2][c2], W + (size_t)(k0 + r2) * D_ + bn + c2);
        }
        cp_commit();
    }

    for (int t = 0; t < 32; t++) {
        if (t + 1 < 32) {
            int k0 = (t + 1) * 32;
            int buf = (t + 1) & 1;
#pragma unroll
            for (int it = 0; it < 2; it++) {
                int l = it * 256 + tid;
                int r = l >> 2, c = (l & 3) * 8;
                cpa16(&sm.As[buf][r][c], A + (size_t)(bm + r) * D_ + k0 + c);
                int r2 = l >> 4, c2 = (l & 15) * 8;
                cpa16(&sm.Bs[buf][r2][c2], W + (size_t)(k0 + r2) * D_ + bn + c2);
            }
        }
        cp_commit();
        cp_wait1();
        __syncthreads();

        int buf = t & 1;
#pragma unroll
        for (int kk = 0; kk < 2; kk++) {
            wmma::fragment<wmma::matrix_a, 16, 16, 16, __nv_bfloat16, wmma::row_major> af[2];
            wmma::fragment<wmma::matrix_b, 16, 16, 16, __nv_bfloat16, wmma::row_major> bfr[4];
#pragma unroll
            for (int i = 0; i < 2; i++)
                wmma::load_matrix_sync(af[i], &sm.As[buf][32 * wm + 16 * i][16 * kk], AS_);
#pragma unroll
            for (int j = 0; j < 4; j++)
                wmma::load_matrix_sync(bfr[j], &sm.Bs[buf][16 * kk][64 * wn + 16 * j], BS_);
#pragma unroll
            for (int i = 0; i < 2; i++)
#pragma unroll
                for (int j = 0; j < 4; j++)
                    wmma::mma_sync(acc[i][j], af[i], bfr[j], acc[i][j]);
        }
        __syncthreads();
    }

    // epilogue: per-fragment through per-warp scratch
#pragma unroll
    for (int i = 0; i < 2; i++) {
#pragma unroll
        for (int j = 0; j < 4; j++) {
            wmma::store_matrix_sync(&sm.scratch[w][0][0], acc[i][j], 20, wmma::mem_row_major);
            __syncwarp();
            int r = lane >> 1, c0 = (lane & 1) * 8;
            int m = bm + 32 * wm + 16 * i + r;
            int n = bn + 64 * wn + 16 * j + c0;
            float v[8];
#pragma unroll
            for (int jj = 0; jj < 8; jj++)
                v[jj] = sm.scratch[w][r][c0 + jj] + bias[n + jj];

            if (heads_mode) {
                int b = m >> 10, s = m & 1023;
                int h = n >> 6, hd = n & 63;
                union { uint4 u; __nv_bfloat16 h8[8]; } pk;
#pragma unroll
                for (int jj = 0; jj < 8; jj++) pk.h8[jj] = __float2bfloat16_rn(v[jj]);
                *(uint4*)(OutB + (((size_t)((b << 4) + h)) << 16) + (s << 6) + hd) = pk.u;
            } else {
                size_t off = (size_t)m * D_ + n;
                float4 r0 = *(const float4*)(resid + off);
                float4 r1 = *(const float4*)(resid + off + 4);
                float4 o0 = make_float4(v[0] + r0.x, v[1] + r0.y, v[2] + r0.z, v[3] + r0.w);
                float4 o1 = make_float4(v[4] + r1.x, v[5] + r1.y, v[6] + r1.z, v[7] + r1.w);
                *(float4*)(OutF + off)     = o0;
                *(float4*)(OutF + off + 4) = o1;
            }
            __syncwarp();
        }
    }
}

// ---------------------------------------------------------------------------
// Attention, wmma bf16. Block = (b,h) x 128-query tile. 8 warps (4x2).
// No online softmax: scores bounded, masked terms underflow to exact 0,
// so PV accumulators persist in fragments across all 8 key tiles.
// ---------------------------------------------------------------------------
struct AttnSmem {
    __nv_bfloat16 Qs[128][72];
    __nv_bfloat16 Ks[128][72];
    __nv_bfloat16 Vs[128][72];
    __nv_bfloat16 Pb[128][136];
    float scratch[8][16][20];
    float rowsum[128][2];
    float Ms[128];
};
#define ATTN_SMEM_BYTES sizeof(AttnSmem)

__global__ __launch_bounds__(256, 2) void attn_kernel(
    const __nv_bfloat16* __restrict__ Q, const __nv_bfloat16* __restrict__ K,
    const __nv_bfloat16* __restrict__ V, const int* __restrict__ mask,
    __nv_bfloat16* __restrict__ ctx)
{
    extern __shared__ char smraw[];
    AttnSmem* sm = (AttnSmem*)smraw;

    const int tid = threadIdx.x;
    const int w = tid >> 5, lane = tid & 31;
    const int wm = w >> 1, wn = w & 1;
    const int bh = blockIdx.y;
    const int b = bh >> 4, h = bh & 15;
    const int q0 = blockIdx.x * 128;

    const __nv_bfloat16* Qp = Q + (((size_t)bh) << 16) + (size_t)q0 * HD_;
    const __nv_bfloat16* Kp = K + (((size_t)bh) << 16);
    const __nv_bfloat16* Vp = V + (((size_t)bh) << 16);
    const int* mp = mask + b * S_;

    // load Q tile
#pragma unroll
    for (int it = 0; it < 4; it++) {
        int l = it * 256 + tid;
        int r = l >> 3, c = (l & 7) * 8;
        *(uint4*)&sm->Qs[r][c] = *(const uint4*)(Qp + (size_t)r * HD_ + c);
    }
    // init rowsums
    sm->rowsum[tid >> 1][tid & 1] = 0.0f;

    wmma::fragment<wmma::accumulator, 16, 16, 16, float> of[2][2];
#pragma unroll
    for (int i = 0; i < 2; i++)
#pragma unroll
        for (int j = 0; j < 2; j++) wmma::fill_fragment(of[i][j], 0.0f);

    for (int k0 = 0; k0 < S_; k0 += 128) {
        __syncthreads();  // prior PV reads done before overwriting K/V
        // load K/V tiles + mask
#pragma unroll
        for (int it = 0; it < 4; it++) {
            int l = it * 256 + tid;
            int r = l >> 3, c = (l & 7) * 8;
            *(uint4*)&sm->Ks[r][c] = *(const uint4*)(Kp + (size_t)(k0 + r) * HD_ + c);
            *(uint4*)&sm->Vs[r][c] = *(const uint4*)(Vp + (size_t)(k0 + r) * HD_ + c);
        }
        if (tid < 128) sm->Ms[tid] = NINF_ * (float)mp[k0 + tid];
        __syncthreads();

        // scores in two 32-col halves to cap register pressure
#pragma unroll
        for (int jh = 0; jh < 2; jh++) {
            wmma::fragment<wmma::accumulator, 16, 16, 16, float> sf[2][2];
#pragma unroll
            for (int i = 0; i < 2; i++)
#pragma unroll
                for (int j = 0; j < 2; j++) wmma::fill_fragment(sf[i][j], 0.0f);

#pragma unroll
            for (int kk = 0; kk < 4; kk++) {
                wmma::fragment<wmma::matrix_a, 16, 16, 16, __nv_bfloat16, wmma::row_major> af[2];
                wmma::fragment<wmma::matrix_b, 16, 16, 16, __nv_bfloat16, wmma::col_major> kf[2];
#pragma unroll
                for (int i = 0; i < 2; i++)
                    wmma::load_matrix_sync(af[i], &sm->Qs[32 * wm + 16 * i][16 * kk], 72);
#pragma unroll
                for (int j = 0; j < 2; j++)
                    wmma::load_matrix_sync(kf[j], &sm->Ks[64 * wn + 16 * (2 * jh + j)][16 * kk], 72);
#pragma unroll
                for (int i = 0; i < 2; i++)
#pragma unroll
                    for (int j = 0; j < 2; j++)
                        wmma::mma_sync(sf[i][j], af[i], kf[j], sf[i][j]);
            }

            // scale + mask + exp -> P (bf16), rowsum accumulation
#pragma unroll
            for (int i = 0; i < 2; i++) {
#pragma unroll
                for (int j = 0; j < 2; j++) {
                    wmma::store_matrix_sync(&sm->scratch[w][0][0], sf[i][j], 20, wmma::mem_row_major);
                    __syncwarp();
                    int r = lane >> 1, c0 = (lane & 1) * 8;
                    int gr = 32 * wm + 16 * i + r;
                    int gc = 64 * wn + 16 * (2 * jh + j) + c0;
                    float p[8];
                    float part = 0.0f;
#pragma unroll
                    for (int jj = 0; jj < 8; jj++) {
                        p[jj] = __expf(sm->scratch[w][r][c0 + jj] * 0.125f + sm->Ms[gc + jj]);
                        part += p[jj];
                    }
                    part += __shfl_xor_sync(0xffffffffu, part, 1);
                    if ((lane & 1) == 0) sm->rowsum[gr][wn] += part;
                    union { uint4 u; __nv_bfloat16 h8[8]; } pk;
#pragma unroll
                    for (int jj = 0; jj < 8; jj++) pk.h8[jj] = __float2bfloat16_rn(p[jj]);
                    *(uint4*)&sm->Pb[gr][gc] = pk.u;
                    __syncwarp();
                }
            }
        }
        __syncthreads();  // P complete

        // O += P @ V
#pragma unroll
        for (int kk = 0; kk < 8; kk++) {
            wmma::fragment<wmma::matrix_a, 16, 16, 16, __nv_bfloat16, wmma::row_major> pf[2];
            wmma::fragment<wmma::matrix_b, 16, 16, 16, __nv_bfloat16, wmma::row_major> vf[2];
#pragma unroll
            for (int i = 0; i < 2; i++)
                wmma::load_matrix_sync(pf[i], &sm->Pb[32 * wm + 16 * i][16 * kk], 136);
#pragma unroll
            for (int j = 0; j < 2; j++)
                wmma::load_matrix_sync(vf[j], &sm->Vs[16 * kk][32 * wn + 16 * j], 72);
#pragma unroll
            for (int i = 0; i < 2; i++)
#pragma unroll
                for (int j = 0; j < 2; j++)
                    wmma::mma_sync(of[i][j], pf[i], vf[j], of[i][j]);
        }
    }
    __syncthreads();

    // write ctx (bf16, [B,S,D]) scaled by 1/rowsum
#pragma unroll
    for (int i = 0; i < 2; i++) {
#pragma unroll
        for (int j = 0; j < 2; j++) {
            wmma::store_matrix_sync(&sm->scratch[w][0][0], of[i][j], 20, wmma::mem_row_major);
            __syncwarp();
            int r = lane >> 1, c0 = (lane & 1) * 8;
            int gr = 32 * wm + 16 * i + r;
            int gc = 32 * wn + 16 * j + c0;
            float inv = 1.0f / (sm->rowsum[gr][0] + sm->rowsum[gr][1]);
            union { uint4 u; __nv_bfloat16 h8[8]; } pk;
#pragma unroll
            for (int jj = 0; jj < 8; jj++)
                pk.h8[jj] = __float2bfloat16_rn(sm->scratch[w][r][c0 + jj] * inv);
            size_t off = (size_t)(b * S_ + q0 + gr) * D_ + h * HD_ + gc;
            *(uint4*)(ctx + off) = pk.u;
            __syncwarp();
        }
    }
}

// ---------------------------------------------------------------------------
// Row LayerNorm over [M, 1024]
// ---------------------------------------------------------------------------
__global__ __launch_bounds__(256) void ln_kernel(
    const float* __restrict__ Y, const float* __restrict__ gamma,
    const float* __restrict__ beta, float* __restrict__ O)
{
    __shared__ float red[16];
    const int row = blockIdx.x;
    const int t = threadIdx.x;
    const float* yr = Y + (size_t)row * D_;
    float4 v = *(const float4*)(yr + t * 4);
    float s  = v.x + v.y + v.z + v.w;
    float sq = v.x * v.x + v.y * v.y + v.z * v.z + v.w * v.w;
#pragma unroll
    for (int o = 16; o; o >>= 1) {
        s  += __shfl_xor_sync(0xffffffffu, s, o);
        sq += __shfl_xor_sync(0xffffffffu, sq, o);
    }
    int w = t >> 5;
    if ((t & 31) == 0) { red[w] = s; red[8 + w] = sq; }
    __syncthreads();
    if (t < 32) {
        s  = (t < 8) ? red[t] : 0.f;
        sq = (t < 8) ? red[8 + t] : 0.f;
#pragma unroll
        for (int o = 4; o; o >>= 1) {
            s  += __shfl_xor_sync(0xffffffffu, s, o);
            sq += __shfl_xor_sync(0xffffffffu, sq, o);
        }
        if (t == 0) { red[0] = s; red[1] = sq; }
    }
    __syncthreads();
    float mu  = red[0] * (1.0f / D_);
    float var = red[1] * (1.0f / D_) - mu * mu;
    float rstd = rsqrtf(var + 1e-6f);
    float4 g  = *(const float4*)(gamma + t * 4);
    float4 be = *(const float4*)(beta + t * 4);
    float4 o;
    o.x = (v.x - mu) * rstd * g.x + be.x;
    o.y = (v.y - mu) * rstd * g.y + be.y;
    o.z = (v.z - mu) * rstd * g.z + be.z;
    o.w = (v.w - mu) * rstd * g.w + be.w;
    *(float4*)(O + (size_t)row * D_ + t * 4) = o;
}

// ---------------------------------------------------------------------------
// Launch
// ---------------------------------------------------------------------------
extern "C" void kernel_launch(void* const* d_in, const int* in_sizes, int n_in,
                              void* d_out, int out_size)
{
    const float* x     = (const float*)d_in[0];
    const int*   mask  = (const int*)d_in[1];
    const float* wq    = (const float*)d_in[2];
    const float* bq    = (const float*)d_in[3];
    const float* wk    = (const float*)d_in[4];
    const float* bk    = (const float*)d_in[5];
    const float* wv    = (const float*)d_in[6];
    const float* bv    = (const float*)d_in[7];
    const float* wo    = (const float*)d_in[8];
    const float* bo    = (const float*)d_in[9];
    const float* gamma = (const float*)d_in[10];
    const float* beta  = (const float*)d_in[11];
    float* out = (float*)d_out;

    __nv_bfloat16 *xb, *wqb, *wkb, *wvb, *wob, *Qb, *Kb, *Vb, *ctxb;
    float* yp;
    cudaGetSymbolAddress((void**)&xb,  g_xb);
    cudaGetSymbolAddress((void**)&wqb, g_wqb);
    cudaGetSymbolAddress((void**)&wkb, g_wkb);
    cudaGetSymbolAddress((void**)&wvb, g_wvb);
    cudaGetSymbolAddress((void**)&wob, g_wob);
    cudaGetSymbolAddress((void**)&Qb,  g_Qb);
    cudaGetSymbolAddress((void**)&Kb,  g_Kb);
    cudaGetSymbolAddress((void**)&Vb,  g_Vb);
    cudaGetSymbolAddress((void**)&ctxb, g_ctxb);
    cudaGetSymbolAddress((void**)&yp,  g_y);

    cudaFuncSetAttribute(attn_kernel,
                         cudaFuncAttributeMaxDynamicSharedMemorySize,
                         (int)ATTN_SMEM_BYTES);

    // conversions
    f2bf_kernel<<<(M_ * D_) / 1024, 256>>>(x,  xb,  M_ * D_);
    f2bf_kernel<<<(D_ * D_) / 1024, 256>>>(wq, wqb, D_ * D_);
    f2bf_kernel<<<(D_ * D_) / 1024, 256>>>(wk, wkb, D_ * D_);
    f2bf_kernel<<<(D_ * D_) / 1024, 256>>>(wv, wvb, D_ * D_);
    f2bf_kernel<<<(D_ * D_) / 1024, 256>>>(wo, wob, D_ * D_);

    dim3 gGemm(D_ / 128, M_ / 128);   // (8, 64)
    gemm_bf16_kernel<<<gGemm, 256>>>(xb, wqb, bq, nullptr, Qb, nullptr, 1);
    gemm_bf16_kernel<<<gGemm, 256>>>(xb, wkb, bk, nullptr, Kb, nullptr, 1);
    gemm_bf16_kernel<<<gGemm, 256>>>(xb, wvb, bv, nullptr, Vb, nullptr, 1);

    dim3 gAttn(S_ / 128, B_ * H_);    // (8, 128)
    attn_kernel<<<gAttn, 256, ATTN_SMEM_BYTES>>>(Qb, Kb, Vb, mask, ctxb);

    gemm_bf16_kernel<<<gGemm, 256>>>(ctxb, wob, bo, x, nullptr, yp, 0);

    ln_kernel<<<M_, 256>>>(yp, gamma, beta, out);
}

// round 4
// speedup vs baseline: 5.4304x; 1.3397x over previous
#include <cuda_runtime.h>
#include <cuda_bf16.h>
#include <math.h>
#include <cstdint>

#define B_  8
#define S_  1024
#define H_  16
#define HD_ 64
#define D_  1024
#define M_  (B_ * S_)       // 8192
#define NINF_ (-10000.0f)

// ---------------- scratch (no allocs allowed) ----------------
__device__ __nv_bfloat16 g_xb[M_ * D_];
__device__ __nv_bfloat16 g_wqt[D_ * D_];   // transposed [N][K]
__device__ __nv_bfloat16 g_wkt[D_ * D_];
__device__ __nv_bfloat16 g_wvt[D_ * D_];
__device__ __nv_bfloat16 g_wot[D_ * D_];
__device__ __nv_bfloat16 g_Qb[M_ * D_];    // [B*H][S][HD]
__device__ __nv_bfloat16 g_Kb[M_ * D_];
__device__ __nv_bfloat16 g_Vb[M_ * D_];
__device__ __nv_bfloat16 g_ctxb[M_ * D_];  // [B*S][D]
__device__ float g_y[M_ * D_];

// ---------------- helpers ----------------
__device__ __forceinline__ uint32_t smem_u32(const void* p) {
    uint32_t a;
    asm("{ .reg .u64 t; cvta.to.shared.u64 t, %1; cvt.u32.u64 %0, t; }"
        : "=r"(a) : "l"(p));
    return a;
}
__device__ __forceinline__ void cpa16s(uint32_t s, const void* g) {
    asm volatile("cp.async.cg.shared.global [%0], [%1], 16;\n" :: "r"(s), "l"(g));
}
__device__ __forceinline__ void cp_commit() { asm volatile("cp.async.commit_group;\n"); }
__device__ __forceinline__ void cp_wait1()  { asm volatile("cp.async.wait_group 1;\n" ::: "memory"); }
__device__ __forceinline__ void cp_wait2()  { asm volatile("cp.async.wait_group 2;\n" ::: "memory"); }

__device__ __forceinline__ void ldmx4(uint32_t* r, uint32_t addr) {
    asm volatile("ldmatrix.sync.aligned.m8n8.x4.shared.b16 {%0,%1,%2,%3}, [%4];"
        : "=r"(r[0]), "=r"(r[1]), "=r"(r[2]), "=r"(r[3]) : "r"(addr));
}
__device__ __forceinline__ void ldmx4t(uint32_t* r, uint32_t addr) {
    asm volatile("ldmatrix.sync.aligned.m8n8.x4.trans.shared.b16 {%0,%1,%2,%3}, [%4];"
        : "=r"(r[0]), "=r"(r[1]), "=r"(r[2]), "=r"(r[3]) : "r"(addr));
}
__device__ __forceinline__ void mma16816(float* c, const uint32_t* a,
                                         uint32_t b0, uint32_t b1) {
    asm volatile("mma.sync.aligned.m16n8k16.row.col.f32.bf16.bf16.f32 "
        "{%0,%1,%2,%3}, {%4,%5,%6,%7}, {%8,%9}, {%0,%1,%2,%3};"
        : "+f"(c[0]), "+f"(c[1]), "+f"(c[2]), "+f"(c[3])
        : "r"(a[0]), "r"(a[1]), "r"(a[2]), "r"(a[3]), "r"(b0), "r"(b1));
}
__device__ __forceinline__ uint32_t packbf2(float lo, float hi) {
    __nv_bfloat162 t = __floats2bfloat162_rn(lo, hi);
    return *(uint32_t*)&t;
}

// ---------------- fp32 -> bf16 conversion ----------------
__global__ __launch_bounds__(256) void f2bf_kernel(
    const float* __restrict__ in, __nv_bfloat16* __restrict__ out, int n)
{
    int i = (blockIdx.x * 256 + threadIdx.x) * 4;
    if (i >= n) return;
    float4 v = *(const float4*)(in + i);
    *(__nv_bfloat162*)(out + i)     = __floats2bfloat162_rn(v.x, v.y);
    *(__nv_bfloat162*)(out + i + 2) = __floats2bfloat162_rn(v.z, v.w);
}

// fp32 [K,N] -> bf16 transposed [N,K]  (1024x1024)
__global__ __launch_bounds__(256) void f2bf_t_kernel(
    const float* __restrict__ in, __nv_bfloat16* __restrict__ out)
{
    __shared__ float tile[32][33];
    const int tx = threadIdx.x & 31, tg = threadIdx.x >> 5;
    const int bx = blockIdx.x * 32, by = blockIdx.y * 32;
#pragma unroll
    for (int p = 0; p < 4; p++) {
        int r = tg + p * 8;
        tile[r][tx] = in[(size_t)(by + r) * D_ + bx + tx];
    }
    __syncthreads();
#pragma unroll
    for (int p = 0; p < 4; p++) {
        int r = tg + p * 8;
        out[(size_t)(bx + r) * D_ + by + tx] = __float2bfloat16_rn(tile[tx][r]);
    }
}

// ---------------------------------------------------------------------------
// mma.sync GEMM: C[8192,1024] = A[8192,1024] @ Wt[1024,1024]^T (Wt is [N][K])
// block 128x128, 8 warps 2(m)x4(n), warp tile 64x32, BK=32, 4-stage cp.async.
// heads_mode=1 -> bf16 scatter to [B,H,S,HD]; else fp32 + resid.
// smem per stage: A 128x40 bf16 (10240B) + B 128x40 bf16 (10240B).
// ---------------------------------------------------------------------------
#define GST 10240
#define GBOFF 40960
#define GEMM_SMEM (2 * 40960)

__global__ __launch_bounds__(256, 2) void gemm_mma_kernel(
    const __nv_bfloat16* __restrict__ A, const __nv_bfloat16* __restrict__ Wt,
    const float* __restrict__ bias, const float* __restrict__ resid,
    __nv_bfloat16* __restrict__ OutB, float* __restrict__ OutF, int heads_mode)
{
    extern __shared__ char smraw[];
    const uint32_t sb = smem_u32(smraw);
    const int tid = threadIdx.x;
    const int wid = tid >> 5, lane = tid & 31;
    const int wm = wid >> 2, wn = wid & 3;
    const int bm = blockIdx.y * 128, bn = blockIdx.x * 128;

    const __nv_bfloat16* Ag = A  + (size_t)bm * D_;
    const __nv_bfloat16* Bg = Wt + (size_t)bn * D_;

    float acc[16][4];
#pragma unroll
    for (int i = 0; i < 16; i++)
#pragma unroll
        for (int j = 0; j < 4; j++) acc[i][j] = 0.f;

    // per-thread load coords (2 chunks each for A and B per stage)
    const int lr0 = tid >> 1,            lc0 = (tid & 1) * 16;        // rows 0..127, col 0 or 16
    // chunk layout: idx = i*256+tid; r=idx>>2, c=(idx&3)*8
#define GLOAD(t) do { \
        const uint32_t as = sb + ((t) & 3) * GST; \
        const uint32_t bs = sb + GBOFF + ((t) & 3) * GST; \
        const __nv_bfloat16* ap = Ag + (t) * 32; \
        const __nv_bfloat16* bp = Bg + (t) * 32; \
        _Pragma("unroll") \
        for (int i = 0; i < 2; i++) { \
            int idx = i * 256 + tid; int r = idx >> 2, c = (idx & 3) * 8; \
            cpa16s(as + (uint32_t)(r * 40 + c) * 2, ap + (size_t)r * D_ + c); \
            cpa16s(bs + (uint32_t)(r * 40 + c) * 2, bp + (size_t)r * D_ + c); \
        } \
    } while (0)

    GLOAD(0); cp_commit();
    GLOAD(1); cp_commit();
    GLOAD(2); cp_commit();
    (void)lr0; (void)lc0;

    for (int t = 0; t < 32; t++) {
        cp_wait2();
        __syncthreads();
        if (t + 3 < 32) GLOAD(t + 3);
        cp_commit();

        const uint32_t as = sb + (t & 3) * GST;
        const uint32_t bs = sb + GBOFF + (t & 3) * GST;
#pragma unroll
        for (int kk = 0; kk < 2; kk++) {
            uint32_t a[4][4];
#pragma unroll
            for (int i = 0; i < 4; i++) {
                int row = wm * 64 + i * 16 + (lane & 7) + ((lane >> 3) & 1) * 8;
                int col = kk * 16 + (lane >> 4) * 8;
                ldmx4(a[i], as + (uint32_t)(row * 40 + col) * 2);
            }
            uint32_t b[4][2];
#pragma unroll
            for (int jp = 0; jp < 2; jp++) {
                int row = wn * 32 + jp * 16 + (lane & 7) + ((lane >> 3) & 1) * 8;
                int col = kk * 16 + (lane >> 4) * 8;
                uint32_t r4[4];
                ldmx4(r4, bs + (uint32_t)(row * 40 + col) * 2);
                b[jp * 2][0] = r4[0]; b[jp * 2][1] = r4[2];
                b[jp * 2 + 1][0] = r4[1]; b[jp * 2 + 1][1] = r4[3];
            }
#pragma unroll
            for (int i = 0; i < 4; i++)
#pragma unroll
                for (int j = 0; j < 4; j++)
                    mma16816(acc[i * 4 + j], a[i], b[j][0], b[j][1]);
        }
        __syncthreads();
    }

    // epilogue: direct from registers
#pragma unroll
    for (int i = 0; i < 4; i++) {
        const int m0 = bm + wm * 64 + i * 16 + (lane >> 2);
#pragma unroll
        for (int j = 0; j < 4; j++) {
            const int n = bn + wn * 32 + j * 8 + 2 * (lane & 3);
            const float2 bb = *(const float2*)(bias + n);
            float v0 = acc[i * 4 + j][0] + bb.x;
            float v1 = acc[i * 4 + j][1] + bb.y;
            float v2 = acc[i * 4 + j][2] + bb.x;
            float v3 = acc[i * 4 + j][3] + bb.y;
            if (heads_mode) {
                const int h = n >> 6, hd = n & 63;
                {
                    int b = m0 >> 10, s = m0 & 1023;
                    *(__nv_bfloat162*)(OutB + (((size_t)((b << 4) + h)) << 16)
                                       + ((size_t)s << 6) + hd)
                        = __floats2bfloat162_rn(v0, v1);
                }
                {
                    int m1 = m0 + 8;
                    int b = m1 >> 10, s = m1 & 1023;
                    *(__nv_bfloat162*)(OutB + (((size_t)((b << 4) + h)) << 16)
                                       + ((size_t)s << 6) + hd)
                        = __floats2bfloat162_rn(v2, v3);
                }
            } else {
                size_t off0 = (size_t)m0 * D_ + n;
                size_t off1 = (size_t)(m0 + 8) * D_ + n;
                float2 r0 = *(const float2*)(resid + off0);
                float2 r1 = *(const float2*)(resid + off1);
                *(float2*)(OutF + off0) = make_float2(v0 + r0.x, v1 + r0.y);
                *(float2*)(OutF + off1) = make_float2(v2 + r1.x, v3 + r1.y);
            }
        }
    }
#undef GLOAD
}

// ---------------------------------------------------------------------------
// Attention, mma.sync. Block = (b,h) x 128 q rows. 8 warps, warp = 16 q rows
// x ALL 128 keys -> softmax entirely in registers, P repacked to A-fragments.
// K/V/mask double-buffered via cp.async. No online rescale needed: scores
// bounded, masked lanes get exactly -1e4 -> exp underflows to ~0 like ref.
// ---------------------------------------------------------------------------
#define AQOFF 0
#define AKOFF 18432
#define AVOFF (18432 + 36864)
#define AMOFF 92160
#define ATTN_SMEM (92160 + 1024)

__global__ __launch_bounds__(256, 1) void attn_kernel(
    const __nv_bfloat16* __restrict__ Q, const __nv_bfloat16* __restrict__ K,
    const __nv_bfloat16* __restrict__ V, const int* __restrict__ mask,
    __nv_bfloat16* __restrict__ ctx)
{
    extern __shared__ char smraw[];
    const uint32_t sb = smem_u32(smraw);
    const int tid = threadIdx.x;
    const int wid = tid >> 5, lane = tid & 31;
    const int bh = blockIdx.y;
    const int b = bh >> 4, h = bh & 15;
    const int q0 = blockIdx.x * 128;

    const __nv_bfloat16* Qp = Q + (((size_t)bh) << 16) + (size_t)q0 * HD_;
    const __nv_bfloat16* Kp = K + (((size_t)bh) << 16);
    const __nv_bfloat16* Vp = V + (((size_t)bh) << 16);
    const int* mp = mask + b * S_;

    // prefetch Q tile (stays whole kernel)
#pragma unroll
    for (int i = 0; i < 4; i++) {
        int idx = i * 256 + tid;
        int r = idx >> 3, c = (idx & 7) * 8;
        cpa16s(sb + AQOFF + (uint32_t)(r * 72 + c) * 2, Qp + (size_t)r * HD_ + c);
    }
#define LOADKV(it, buf) do { \
        const int k0 = (it) * 128; \
        _Pragma("unroll") \
        for (int i = 0; i < 4; i++) { \
            int idx = i * 256 + tid; int r = idx >> 3, c = (idx & 7) * 8; \
            cpa16s(sb + AKOFF + (buf) * 18432 + (uint32_t)(r * 72 + c) * 2, \
                   Kp + (size_t)(k0 + r) * HD_ + c); \
            cpa16s(sb + AVOFF + (buf) * 18432 + (uint32_t)(r * 72 + c) * 2, \
                   Vp + (size_t)(k0 + r) * HD_ + c); \
        } \
        if (tid < 32) cpa16s(sb + AMOFF + (buf) * 512 + tid * 16, mp + k0 + tid * 4); \
    } while (0)

    LOADKV(0, 0);
    cp_commit();

    uint32_t qf[4][4];
    float oacc[8][4];
#pragma unroll
    for (int i = 0; i < 8; i++)
#pragma unroll
        for (int j = 0; j < 4; j++) oacc[i][j] = 0.f;
    float lsum0 = 0.f, lsum1 = 0.f;

    for (int it = 0; it < 8; it++) {
        if (it + 1 < 8) LOADKV(it + 1, (it + 1) & 1);
        cp_commit();
        cp_wait1();
        __syncthreads();

        if (it == 0) {
#pragma unroll
            for (int kk = 0; kk < 4; kk++) {
                int row = wid * 16 + (lane & 7) + ((lane >> 3) & 1) * 8;
                int col = kk * 16 + (lane >> 4) * 8;
                ldmx4(qf[kk], sb + AQOFF + (uint32_t)(row * 72 + col) * 2);
            }
        }

        const int buf = it & 1;
        const uint32_t ksb = sb + AKOFF + buf * 18432;
        const uint32_t vsb = sb + AVOFF + buf * 18432;
        const int* msk = (const int*)(smraw + AMOFF + buf * 512);

        // scores: 16 n-tiles (128 keys), k = hd (4 ksteps)
        float sacc[16][4];
#pragma unroll
        for (int i = 0; i < 16; i++)
#pragma unroll
            for (int j = 0; j < 4; j++) sacc[i][j] = 0.f;

#pragma unroll
        for (int kk = 0; kk < 4; kk++) {
#pragma unroll
            for (int jp = 0; jp < 8; jp++) {
                int row = jp * 16 + (lane & 7) + ((lane >> 3) & 1) * 8;
                int col = kk * 16 + (lane >> 4) * 8;
                uint32_t r4[4];
                ldmx4(r4, ksb + (uint32_t)(row * 72 + col) * 2);
                mma16816(sacc[jp * 2],     qf[kk], r4[0], r4[2]);
                mma16816(sacc[jp * 2 + 1], qf[kk], r4[1], r4[3]);
            }
        }

        // softmax (register-resident), pack P into A-fragments
        uint32_t pf[8][4];
#pragma unroll
        for (int j = 0; j < 16; j++) {
            const int n0 = j * 8 + 2 * (lane & 3);
            const float mk0 = NINF_ * (float)msk[n0];
            const float mk1 = NINF_ * (float)msk[n0 + 1];
            float e0 = __expf(fmaf(sacc[j][0], 0.125f, mk0));
            float e1 = __expf(fmaf(sacc[j][1], 0.125f, mk1));
            float e2 = __expf(fmaf(sacc[j][2], 0.125f, mk0));
            float e3 = __expf(fmaf(sacc[j][3], 0.125f, mk1));
            lsum0 += e0 + e1;
            lsum1 += e2 + e3;
            const int kk2 = j >> 1;
            if ((j & 1) == 0) {
                pf[kk2][0] = packbf2(e0, e1);
                pf[kk2][1] = packbf2(e2, e3);
            } else {
                pf[kk2][2] = packbf2(e0, e1);
                pf[kk2][3] = packbf2(e2, e3);
            }
        }

        // O += P @ V  (V fragments via ldmatrix.trans)
#pragma unroll
        for (int kk2 = 0; kk2 < 8; kk2++) {
#pragma unroll
            for (int jp = 0; jp < 4; jp++) {
                int row = kk2 * 16 + (lane & 7) + ((lane >> 3) & 1) * 8;
                int col = jp * 16 + (lane >> 4) * 8;
                uint32_t r4[4];
                ldmx4t(r4, vsb + (uint32_t)(row * 72 + col) * 2);
                mma16816(oacc[jp * 2],     pf[kk2], r4[0], r4[1]);
                mma16816(oacc[jp * 2 + 1], pf[kk2], r4[2], r4[3]);
            }
        }
        __syncthreads();
    }

    // rowsum reduce across quad (4 lanes share a row)
    lsum0 += __shfl_xor_sync(0xffffffffu, lsum0, 1);
    lsum0 += __shfl_xor_sync(0xffffffffu, lsum0, 2);
    lsum1 += __shfl_xor_sync(0xffffffffu, lsum1, 1);
    lsum1 += __shfl_xor_sync(0xffffffffu, lsum1, 2);
    const float inv0 = 1.0f / lsum0;
    const float inv1 = 1.0f / lsum1;

    const int row0 = q0 + wid * 16 + (lane >> 2);
#pragma unroll
    for (int j2 = 0; j2 < 8; j2++) {
        const int col = h * HD_ + j2 * 8 + 2 * (lane & 3);
        size_t off0 = (size_t)(b * S_ + row0) * D_ + col;
        size_t off1 = (size_t)(b * S_ + row0 + 8) * D_ + col;
        *(__nv_bfloat162*)(ctx + off0) =
            __floats2bfloat162_rn(oacc[j2][0] * inv0, oacc[j2][1] * inv0);
        *(__nv_bfloat162*)(ctx + off1) =
            __floats2bfloat162_rn(oacc[j2][2] * inv1, oacc[j2][3] * inv1);
    }
#undef LOADKV
}

// ---------------------------------------------------------------------------
// Row LayerNorm over [M, 1024]
// ---------------------------------------------------------------------------
__global__ __launch_bounds__(256) void ln_kernel(
    const float* __restrict__ Y, const float* __restrict__ gamma,
    const float* __restrict__ beta, float* __restrict__ O)
{
    __shared__ float red[16];
    const int row = blockIdx.x;
    const int t = threadIdx.x;
    const float* yr = Y + (size_t)row * D_;
    float4 v = *(const float4*)(yr + t * 4);
    float s  = v.x + v.y + v.z + v.w;
    float sq = v.x * v.x + v.y * v.y + v.z * v.z + v.w * v.w;
#pragma unroll
    for (int o = 16; o; o >>= 1) {
        s  += __shfl_xor_sync(0xffffffffu, s, o);
        sq += __shfl_xor_sync(0xffffffffu, sq, o);
    }
    int w = t >> 5;
    if ((t & 31) == 0) { red[w] = s; red[8 + w] = sq; }
    __syncthreads();
    if (t < 32) {
        s  = (t < 8) ? red[t] : 0.f;
        sq = (t < 8) ? red[8 + t] : 0.f;
#pragma unroll
        for (int o = 4; o; o >>= 1) {
            s  += __shfl_xor_sync(0xffffffffu, s, o);
            sq += __shfl_xor_sync(0xffffffffu, sq, o);
        }
        if (t == 0) { red[0] = s; red[1] = sq; }
    }
    __syncthreads();
    float mu  = red[0] * (1.0f / D_);
    float var = red[1] * (1.0f / D_) - mu * mu;
    float rstd = rsqrtf(var + 1e-6f);
    float4 g  = *(const float4*)(gamma + t * 4);
    float4 be = *(const float4*)(beta + t * 4);
    float4 o;
    o.x = (v.x - mu) * rstd * g.x + be.x;
    o.y = (v.y - mu) * rstd * g.y + be.y;
    o.z = (v.z - mu) * rstd * g.z + be.z;
    o.w = (v.w - mu) * rstd * g.w + be.w;
    *(float4*)(O + (size_t)row * D_ + t * 4) = o;
}

// ---------------------------------------------------------------------------
// Launch
// ---------------------------------------------------------------------------
extern "C" void kernel_launch(void* const* d_in, const int* in_sizes, int n_in,
                              void* d_out, int out_size)
{
    const float* x     = (const float*)d_in[0];
    const int*   mask  = (const int*)d_in[1];
    const float* wq    = (const float*)d_in[2];
    const float* bq    = (const float*)d_in[3];
    const float* wk    = (const float*)d_in[4];
    const float* bk    = (const float*)d_in[5];
    const float* wv    = (const float*)d_in[6];
    const float* bv    = (const float*)d_in[7];
    const float* wo    = (const float*)d_in[8];
    const float* bo    = (const float*)d_in[9];
    const float* gamma = (const float*)d_in[10];
    const float* beta  = (const float*)d_in[11];
    float* out = (float*)d_out;

    __nv_bfloat16 *xb, *wqt, *wkt, *wvt, *wot, *Qb, *Kb, *Vb, *ctxb;
    float* yp;
    cudaGetSymbolAddress((void**)&xb,  g_xb);
    cudaGetSymbolAddress((void**)&wqt, g_wqt);
    cudaGetSymbolAddress((void**)&wkt, g_wkt);
    cudaGetSymbolAddress((void**)&wvt, g_wvt);
    cudaGetSymbolAddress((void**)&wot, g_wot);
    cudaGetSymbolAddress((void**)&Qb,  g_Qb);
    cudaGetSymbolAddress((void**)&Kb,  g_Kb);
    cudaGetSymbolAddress((void**)&Vb,  g_Vb);
    cudaGetSymbolAddress((void**)&ctxb, g_ctxb);
    cudaGetSymbolAddress((void**)&yp,  g_y);

    cudaFuncSetAttribute(gemm_mma_kernel,
                         cudaFuncAttributeMaxDynamicSharedMemorySize, GEMM_SMEM);
    cudaFuncSetAttribute(attn_kernel,
                         cudaFuncAttributeMaxDynamicSharedMemorySize, ATTN_SMEM);

    // conversions (x straight; weights transposed to [N][K])
    f2bf_kernel<<<(M_ * D_) / 1024, 256>>>(x, xb, M_ * D_);
    dim3 gT(32, 32);
    f2bf_t_kernel<<<gT, 256>>>(wq, wqt);
    f2bf_t_kernel<<<gT, 256>>>(wk, wkt);
    f2bf_t_kernel<<<gT, 256>>>(wv, wvt);
    f2bf_t_kernel<<<gT, 256>>>(wo, wot);

    dim3 gGemm(D_ / 128, M_ / 128);   // (8, 64)
    gemm_mma_kernel<<<gGemm, 256, GEMM_SMEM>>>(xb, wqt, bq, nullptr, Qb, nullptr, 1);
    gemm_mma_kernel<<<gGemm, 256, GEMM_SMEM>>>(xb, wkt, bk, nullptr, Kb, nullptr, 1);
    gemm_mma_kernel<<<gGemm, 256, GEMM_SMEM>>>(xb, wvt, bv, nullptr, Vb, nullptr, 1);

    dim3 gAttn(S_ / 128, B_ * H_);    // (8, 128)
    attn_kernel<<<gAttn, 256, ATTN_SMEM>>>(Qb, Kb, Vb, mask, ctxb);

    gemm_mma_kernel<<<gGemm, 256, GEMM_SMEM>>>(ctxb, wot, bo, x, nullptr, yp, 0);

    ln_kernel<<<M_, 256>>>(yp, gamma, beta, out);
}

// round 5
// speedup vs baseline: 6.6559x; 1.2257x over previous
#include <cuda_runtime.h>
#include <cuda_bf16.h>
#include <math.h>
#include <cstdint>

#define B_  8
#define S_  1024
#define H_  16
#define HD_ 64
#define D_  1024
#define M_  (B_ * S_)       // 8192
#define NINF_ (-10000.0f)

// ---------------- scratch (no allocs allowed) ----------------
__device__ __nv_bfloat16 g_xb[M_ * D_];
__device__ __nv_bfloat16 g_wqb[D_ * D_];   // native [K][N] layout, bf16
__device__ __nv_bfloat16 g_wkb[D_ * D_];
__device__ __nv_bfloat16 g_wvb[D_ * D_];
__device__ __nv_bfloat16 g_wob[D_ * D_];
__device__ __nv_bfloat16 g_Qb[M_ * D_];    // [B*H][S][HD]
__device__ __nv_bfloat16 g_Kb[M_ * D_];
__device__ __nv_bfloat16 g_Vb[M_ * D_];
__device__ __nv_bfloat16 g_ctxb[M_ * D_];  // [B*S][D]
__device__ float g_y[M_ * D_];

// ---------------- helpers ----------------
__device__ __forceinline__ uint32_t smem_u32(const void* p) {
    uint32_t a;
    asm("{ .reg .u64 t; cvta.to.shared.u64 t, %1; cvt.u32.u64 %0, t; }"
        : "=r"(a) : "l"(p));
    return a;
}
__device__ __forceinline__ void cpa16s(uint32_t s, const void* g) {
    asm volatile("cp.async.cg.shared.global [%0], [%1], 16;\n" :: "r"(s), "l"(g));
}
__device__ __forceinline__ void cp_commit() { asm volatile("cp.async.commit_group;\n"); }
__device__ __forceinline__ void cp_wait0()  { asm volatile("cp.async.wait_group 0;\n" ::: "memory"); }
__device__ __forceinline__ void cp_wait2()  { asm volatile("cp.async.wait_group 2;\n" ::: "memory"); }

__device__ __forceinline__ void ldmx4(uint32_t* r, uint32_t addr) {
    asm volatile("ldmatrix.sync.aligned.m8n8.x4.shared.b16 {%0,%1,%2,%3}, [%4];"
        : "=r"(r[0]), "=r"(r[1]), "=r"(r[2]), "=r"(r[3]) : "r"(addr));
}
__device__ __forceinline__ void ldmx4t(uint32_t* r, uint32_t addr) {
    asm volatile("ldmatrix.sync.aligned.m8n8.x4.trans.shared.b16 {%0,%1,%2,%3}, [%4];"
        : "=r"(r[0]), "=r"(r[1]), "=r"(r[2]), "=r"(r[3]) : "r"(addr));
}
__device__ __forceinline__ void mma16816(float* c, const uint32_t* a,
                                         uint32_t b0, uint32_t b1) {
    asm volatile("mma.sync.aligned.m16n8k16.row.col.f32.bf16.bf16.f32 "
        "{%0,%1,%2,%3}, {%4,%5,%6,%7}, {%8,%9}, {%0,%1,%2,%3};"
        : "+f"(c[0]), "+f"(c[1]), "+f"(c[2]), "+f"(c[3])
        : "r"(a[0]), "r"(a[1]), "r"(a[2]), "r"(a[3]), "r"(b0), "r"(b1));
}
__device__ __forceinline__ uint32_t packbf2(float lo, float hi) {
    __nv_bfloat162 t = __floats2bfloat162_rn(lo, hi);
    return *(uint32_t*)&t;
}

// ---------------------------------------------------------------------------
// One fused fp32->bf16 conversion for x + 4 weights (no transposes needed).
// ---------------------------------------------------------------------------
#define XN (M_ * D_)          // 8388608
#define WN (D_ * D_)          // 1048576
__global__ __launch_bounds__(256) void cvt_all_kernel(
    const float* __restrict__ x,
    const float* __restrict__ wq, const float* __restrict__ wk,
    const float* __restrict__ wv, const float* __restrict__ wo,
    __nv_bfloat16* __restrict__ xb,
    __nv_bfloat16* __restrict__ wqb, __nv_bfloat16* __restrict__ wkb,
    __nv_bfloat16* __restrict__ wvb, __nv_bfloat16* __restrict__ wob)
{
    long long i = (long long)(blockIdx.x * 256 + threadIdx.x) * 4;
    const float* src;
    __nv_bfloat16* dst;
    long long off;
    if (i < XN)                { src = x;  dst = xb;  off = i; }
    else if (i < XN + WN)      { src = wq; dst = wqb; off = i - XN; }
    else if (i < XN + 2 * WN)  { src = wk; dst = wkb; off = i - XN - WN; }
    else if (i < XN + 3 * WN)  { src = wv; dst = wvb; off = i - XN - 2 * WN; }
    else                       { src = wo; dst = wob; off = i - XN - 3 * WN; }
    float4 v = *(const float4*)(src + off);
    *(__nv_bfloat162*)(dst + off)     = __floats2bfloat162_rn(v.x, v.y);
    *(__nv_bfloat162*)(dst + off + 2) = __floats2bfloat162_rn(v.z, v.w);
}

// ---------------------------------------------------------------------------
// mma.sync GEMM: C[8192,1024] = A[8192,1024] @ W[1024,1024] (W native [K][N])
// block 128x128, 8 warps 2(m)x4(n), warp 64x32, BK=32, 4-stage, 1 sync/iter.
// B fragments via ldmatrix.trans of [K][N] tiles (no weight transpose).
// qkv_mode: gridDim.z=3 selects (wq,bq)->Q, (wk,bk)->K, (wv,bv)->V scatter.
// heads_mode=0: fp32 + resid out.
// smem: A stage 128x40 bf16 (10240B) x4; B stage 32x136 bf16 (8704B) x4.
// ---------------------------------------------------------------------------
#define GAST 10240
#define GBST 8704
#define GBBASE (4 * GAST)
#define GEMM_SMEM (4 * GAST + 4 * GBST)   // 75776

__global__ __launch_bounds__(256, 2) void gemm_mma_kernel(
    const __nv_bfloat16* __restrict__ A,
    const __nv_bfloat16* __restrict__ W0, const __nv_bfloat16* __restrict__ W1,
    const __nv_bfloat16* __restrict__ W2,
    const float* __restrict__ b0p, const float* __restrict__ b1p,
    const float* __restrict__ b2p,
    const float* __restrict__ resid,
    __nv_bfloat16* __restrict__ O0, __nv_bfloat16* __restrict__ O1,
    __nv_bfloat16* __restrict__ O2,
    float* __restrict__ OutF, int heads_mode)
{
    extern __shared__ char smraw[];
    const uint32_t sb = smem_u32(smraw);
    const int tid = threadIdx.x;
    const int wid = tid >> 5, lane = tid & 31;
    const int wm = wid >> 2, wn = wid & 3;
    const int bm = blockIdx.y * 128, bn = blockIdx.x * 128;
    const int z = blockIdx.z;

    const __nv_bfloat16* W = (z == 0) ? W0 : (z == 1) ? W1 : W2;
    const float* bias       = (z == 0) ? b0p : (z == 1) ? b1p : b2p;
    __nv_bfloat16* OutB     = (z == 0) ? O0 : (z == 1) ? O1 : O2;

    const __nv_bfloat16* Ag = A + (size_t)bm * D_;
    const __nv_bfloat16* Wg = W + bn;

    float acc[16][4];
#pragma unroll
    for (int i = 0; i < 16; i++)
#pragma unroll
        for (int j = 0; j < 4; j++) acc[i][j] = 0.f;

#define GLOAD(t) do { \
        const uint32_t as = sb + ((t) & 3) * GAST; \
        const uint32_t bs = sb + GBBASE + ((t) & 3) * GBST; \
        const __nv_bfloat16* ap = Ag + (t) * 32; \
        const __nv_bfloat16* wp = Wg + (size_t)((t) * 32) * D_; \
        _Pragma("unroll") \
        for (int i = 0; i < 2; i++) { \
            int idx = i * 256 + tid; \
            int ra = idx >> 2, ca = (idx & 3) * 8; \
            cpa16s(as + (uint32_t)(ra * 40 + ca) * 2, ap + (size_t)ra * D_ + ca); \
            int rb = idx >> 4, cb = (idx & 15) * 8; \
            cpa16s(bs + (uint32_t)(rb * 136 + cb) * 2, wp + (size_t)rb * D_ + cb); \
        } \
    } while (0)

    GLOAD(0); cp_commit();
    GLOAD(1); cp_commit();
    GLOAD(2); cp_commit();

    for (int t = 0; t < 32; t++) {
        cp_wait2();
        __syncthreads();
        if (t + 3 < 32) GLOAD(t + 3);
        cp_commit();

        const uint32_t as = sb + (t & 3) * GAST;
        const uint32_t bs = sb + GBBASE + (t & 3) * GBST;
#pragma unroll
        for (int kk = 0; kk < 2; kk++) {
            uint32_t a[4][4];
#pragma unroll
            for (int i = 0; i < 4; i++) {
                int row = wm * 64 + i * 16 + (lane & 7) + ((lane >> 3) & 1) * 8;
                int col = kk * 16 + (lane >> 4) * 8;
                ldmx4(a[i], as + (uint32_t)(row * 40 + col) * 2);
            }
#pragma unroll
            for (int jp = 0; jp < 2; jp++) {
                int row = kk * 16 + (lane & 7) + ((lane >> 3) & 1) * 8;
                int col = wn * 32 + jp * 16 + (lane >> 4) * 8;
                uint32_t r4[4];
                ldmx4t(r4, bs + (uint32_t)(row * 136 + col) * 2);
#pragma unroll
                for (int i = 0; i < 4; i++) {
                    mma16816(acc[i * 4 + jp * 2],     a[i], r4[0], r4[1]);
                    mma16816(acc[i * 4 + jp * 2 + 1], a[i], r4[2], r4[3]);
                }
            }
        }
        // no trailing sync: next iter's top barrier orders buffer reuse
    }
#undef GLOAD

    // epilogue: direct from registers
#pragma unroll
    for (int i = 0; i < 4; i++) {
        const int m0 = bm + wm * 64 + i * 16 + (lane >> 2);
#pragma unroll
        for (int j = 0; j < 4; j++) {
            const int n = bn + wn * 32 + j * 8 + 2 * (lane & 3);
            const float2 bb = *(const float2*)(bias + n);
            float v0 = acc[i * 4 + j][0] + bb.x;
            float v1 = acc[i * 4 + j][1] + bb.y;
            float v2 = acc[i * 4 + j][2] + bb.x;
            float v3 = acc[i * 4 + j][3] + bb.y;
            if (heads_mode) {
                const int h = n >> 6, hd = n & 63;
                {
                    int b = m0 >> 10, s = m0 & 1023;
                    *(__nv_bfloat162*)(OutB + (((size_t)((b << 4) + h)) << 16)
                                       + ((size_t)s << 6) + hd)
                        = __floats2bfloat162_rn(v0, v1);
                }
                {
                    int m1 = m0 + 8;
                    int b = m1 >> 10, s = m1 & 1023;
                    *(__nv_bfloat162*)(OutB + (((size_t)((b << 4) + h)) << 16)
                                       + ((size_t)s << 6) + hd)
                        = __floats2bfloat162_rn(v2, v3);
                }
            } else {
                size_t off0 = (size_t)m0 * D_ + n;
                size_t off1 = (size_t)(m0 + 8) * D_ + n;
                float2 r0 = *(const float2*)(resid + off0);
                float2 r1 = *(const float2*)(resid + off1);
                *(float2*)(OutF + off0) = make_float2(v0 + r0.x, v1 + r0.y);
                *(float2*)(OutF + off1) = make_float2(v2 + r1.x, v3 + r1.y);
            }
        }
    }
}

// ---------------------------------------------------------------------------
// Attention, mma.sync. Block = (b,h) x 128 q rows. 8 warps, warp = 16 q rows
// x ALL 128 keys -> softmax entirely in registers. 1 sync per key-tile.
// ---------------------------------------------------------------------------
#define AQOFF 0
#define AKOFF 18432
#define AVOFF (18432 + 36864)
#define AMOFF 92160
#define ATTN_SMEM (92160 + 1024)

__global__ __launch_bounds__(256, 1) void attn_kernel(
    const __nv_bfloat16* __restrict__ Q, const __nv_bfloat16* __restrict__ K,
    const __nv_bfloat16* __restrict__ V, const int* __restrict__ mask,
    __nv_bfloat16* __restrict__ ctx)
{
    extern __shared__ char smraw[];
    const uint32_t sb = smem_u32(smraw);
    const int tid = threadIdx.x;
    const int wid = tid >> 5, lane = tid & 31;
    const int bh = blockIdx.y;
    const int b = bh >> 4, h = bh & 15;
    const int q0 = blockIdx.x * 128;

    const __nv_bfloat16* Qp = Q + (((size_t)bh) << 16) + (size_t)q0 * HD_;
    const __nv_bfloat16* Kp = K + (((size_t)bh) << 16);
    const __nv_bfloat16* Vp = V + (((size_t)bh) << 16);
    const int* mp = mask + b * S_;

    // Q tile prefetch (group 0, together with KV tile 0)
#pragma unroll
    for (int i = 0; i < 4; i++) {
        int idx = i * 256 + tid;
        int r = idx >> 3, c = (idx & 7) * 8;
        cpa16s(sb + AQOFF + (uint32_t)(r * 72 + c) * 2, Qp + (size_t)r * HD_ + c);
    }
#define LOADKV(it, buf) do { \
        const int k0 = (it) * 128; \
        _Pragma("unroll") \
        for (int i = 0; i < 4; i++) { \
            int idx = i * 256 + tid; int r = idx >> 3, c = (idx & 7) * 8; \
            cpa16s(sb + AKOFF + (buf) * 18432 + (uint32_t)(r * 72 + c) * 2, \
                   Kp + (size_t)(k0 + r) * HD_ + c); \
            cpa16s(sb + AVOFF + (buf) * 18432 + (uint32_t)(r * 72 + c) * 2, \
                   Vp + (size_t)(k0 + r) * HD_ + c); \
        } \
        if (tid < 32) cpa16s(sb + AMOFF + (buf) * 512 + tid * 16, mp + k0 + tid * 4); \
    } while (0)

    LOADKV(0, 0);
    cp_commit();

    uint32_t qf[4][4];
    float oacc[8][4];
#pragma unroll
    for (int i = 0; i < 8; i++)
#pragma unroll
        for (int j = 0; j < 4; j++) oacc[i][j] = 0.f;
    float lsum0 = 0.f, lsum1 = 0.f;

    for (int it = 0; it < 8; it++) {
        cp_wait0();
        __syncthreads();
        if (it + 1 < 8) LOADKV(it + 1, (it + 1) & 1);
        cp_commit();

        if (it == 0) {
#pragma unroll
            for (int kk = 0; kk < 4; kk++) {
                int row = wid * 16 + (lane & 7) + ((lane >> 3) & 1) * 8;
                int col = kk * 16 + (lane >> 4) * 8;
                ldmx4(qf[kk], sb + AQOFF + (uint32_t)(row * 72 + col) * 2);
            }
        }

        const int buf = it & 1;
        const uint32_t ksb = sb + AKOFF + buf * 18432;
        const uint32_t vsb = sb + AVOFF + buf * 18432;
        const int* msk = (const int*)(smraw + AMOFF + buf * 512);

        float sacc[16][4];
#pragma unroll
        for (int i = 0; i < 16; i++)
#pragma unroll
            for (int j = 0; j < 4; j++) sacc[i][j] = 0.f;

#pragma unroll
        for (int kk = 0; kk < 4; kk++) {
#pragma unroll
            for (int jp = 0; jp < 8; jp++) {
                int row = jp * 16 + (lane & 7) + ((lane >> 3) & 1) * 8;
                int col = kk * 16 + (lane >> 4) * 8;
                uint32_t r4[4];
                ldmx4(r4, ksb + (uint32_t)(row * 72 + col) * 2);
                mma16816(sacc[jp * 2],     qf[kk], r4[0], r4[2]);
                mma16816(sacc[jp * 2 + 1], qf[kk], r4[1], r4[3]);
            }
        }

        // softmax (register-resident), pack P into A-fragments
        uint32_t pf[8][4];
#pragma unroll
        for (int j = 0; j < 16; j++) {
            const int n0 = j * 8 + 2 * (lane & 3);
            const float mk0 = NINF_ * (float)msk[n0];
            const float mk1 = NINF_ * (float)msk[n0 + 1];
            float e0 = __expf(fmaf(sacc[j][0], 0.125f, mk0));
            float e1 = __expf(fmaf(sacc[j][1], 0.125f, mk1));
            float e2 = __expf(fmaf(sacc[j][2], 0.125f, mk0));
            float e3 = __expf(fmaf(sacc[j][3], 0.125f, mk1));
            lsum0 += e0 + e1;
            lsum1 += e2 + e3;
            const int kk2 = j >> 1;
            if ((j & 1) == 0) {
                pf[kk2][0] = packbf2(e0, e1);
                pf[kk2][1] = packbf2(e2, e3);
            } else {
                pf[kk2][2] = packbf2(e0, e1);
                pf[kk2][3] = packbf2(e2, e3);
            }
        }

        // O += P @ V  (V fragments via ldmatrix.trans)
#pragma unroll
        for (int kk2 = 0; kk2 < 8; kk2++) {
#pragma unroll
            for (int jp = 0; jp < 4; jp++) {
                int row = kk2 * 16 + (lane & 7) + ((lane >> 3) & 1) * 8;
                int col = jp * 16 + (lane >> 4) * 8;
                uint32_t r4[4];
                ldmx4t(r4, vsb + (uint32_t)(row * 72 + col) * 2);
                mma16816(oacc[jp * 2],     pf[kk2], r4[0], r4[1]);
                mma16816(oacc[jp * 2 + 1], pf[kk2], r4[2], r4[3]);
            }
        }
        // no trailing sync: next iter's wait+bar orders buffer reuse
    }
#undef LOADKV

    lsum0 += __shfl_xor_sync(0xffffffffu, lsum0, 1);
    lsum0 += __shfl_xor_sync(0xffffffffu, lsum0, 2);
    lsum1 += __shfl_xor_sync(0xffffffffu, lsum1, 1);
    lsum1 += __shfl_xor_sync(0xffffffffu, lsum1, 2);
    const float inv0 = 1.0f / lsum0;
    const float inv1 = 1.0f / lsum1;

    const int row0 = q0 + wid * 16 + (lane >> 2);
#pragma unroll
    for (int j2 = 0; j2 < 8; j2++) {
        const int col = h * HD_ + j2 * 8 + 2 * (lane & 3);
        size_t off0 = (size_t)(b * S_ + row0) * D_ + col;
        size_t off1 = (size_t)(b * S_ + row0 + 8) * D_ + col;
        *(__nv_bfloat162*)(ctx + off0) =
            __floats2bfloat162_rn(oacc[j2][0] * inv0, oacc[j2][1] * inv0);
        *(__nv_bfloat162*)(ctx + off1) =
            __floats2bfloat162_rn(oacc[j2][2] * inv1, oacc[j2][3] * inv1);
    }
}

// ---------------------------------------------------------------------------
// Row LayerNorm over [M, 1024]
// ---------------------------------------------------------------------------
__global__ __launch_bounds__(256) void ln_kernel(
    const float* __restrict__ Y, const float* __restrict__ gamma,
    const float* __restrict__ beta, float* __restrict__ O)
{
    __shared__ float red[16];
    const int row = blockIdx.x;
    const int t = threadIdx.x;
    const float* yr = Y + (size_t)row * D_;
    float4 v = *(const float4*)(yr + t * 4);
    float s  = v.x + v.y + v.z + v.w;
    float sq = v.x * v.x + v.y * v.y + v.z * v.z + v.w * v.w;
#pragma unroll
    for (int o = 16; o; o >>= 1) {
        s  += __shfl_xor_sync(0xffffffffu, s, o);
        sq += __shfl_xor_sync(0xffffffffu, sq, o);
    }
    int w = t >> 5;
    if ((t & 31) == 0) { red[w] = s; red[8 + w] = sq; }
    __syncthreads();
    if (t < 32) {
        s  = (t < 8) ? red[t] : 0.f;
        sq = (t < 8) ? red[8 + t] : 0.f;
#pragma unroll
        for (int o = 4; o; o >>= 1) {
            s  += __shfl_xor_sync(0xffffffffu, s, o);
            sq += __shfl_xor_sync(0xffffffffu, sq, o);
        }
        if (t == 0) { red[0] = s; red[1] = sq; }
    }
    __syncthreads();
    float mu  = red[0] * (1.0f / D_);
    float var = red[1] * (1.0f / D_) - mu * mu;
    float rstd = rsqrtf(var + 1e-6f);
    float4 g  = *(const float4*)(gamma + t * 4);
    float4 be = *(const float4*)(beta + t * 4);
    float4 o;
    o.x = (v.x - mu) * rstd * g.x + be.x;
    o.y = (v.y - mu) * rstd * g.y + be.y;
    o.z = (v.z - mu) * rstd * g.z + be.z;
    o.w = (v.w - mu) * rstd * g.w + be.w;
    *(float4*)(O + (size_t)row * D_ + t * 4) = o;
}

// ---------------------------------------------------------------------------
// Launch
// ---------------------------------------------------------------------------
extern "C" void kernel_launch(void* const* d_in, const int* in_sizes, int n_in,
                              void* d_out, int out_size)
{
    const float* x     = (const float*)d_in[0];
    const int*   mask  = (const int*)d_in[1];
    const float* wq    = (const float*)d_in[2];
    const float* bq    = (const float*)d_in[3];
    const float* wk    = (const float*)d_in[4];
    const float* bk    = (const float*)d_in[5];
    const float* wv    = (const float*)d_in[6];
    const float* bv    = (const float*)d_in[7];
    const float* wo    = (const float*)d_in[8];
    const float* bo    = (const float*)d_in[9];
    const float* gamma = (const float*)d_in[10];
    const float* beta  = (const float*)d_in[11];
    float* out = (float*)d_out;

    __nv_bfloat16 *xb, *wqb, *wkb, *wvb, *wob, *Qb, *Kb, *Vb, *ctxb;
    float* yp;
    cudaGetSymbolAddress((void**)&xb,  g_xb);
    cudaGetSymbolAddress((void**)&wqb, g_wqb);
    cudaGetSymbolAddress((void**)&wkb, g_wkb);
    cudaGetSymbolAddress((void**)&wvb, g_wvb);
    cudaGetSymbolAddress((void**)&wob, g_wob);
    cudaGetSymbolAddress((void**)&Qb,  g_Qb);
    cudaGetSymbolAddress((void**)&Kb,  g_Kb);
    cudaGetSymbolAddress((void**)&Vb,  g_Vb);
    cudaGetSymbolAddress((void**)&ctxb, g_ctxb);
    cudaGetSymbolAddress((void**)&yp,  g_y);

    cudaFuncSetAttribute(gemm_mma_kernel,
                         cudaFuncAttributeMaxDynamicSharedMemorySize, GEMM_SMEM);
    cudaFuncSetAttribute(attn_kernel,
                         cudaFuncAttributeMaxDynamicSharedMemorySize, ATTN_SMEM);

    // one fused conversion (x + 4 weights, native layout)
    cvt_all_kernel<<<(XN + 4 * WN) / 1024, 256>>>(
        x, wq, wk, wv, wo, xb, wqb, wkb, wvb, wob);

    // fused QKV: gridDim.z selects weight/bias/output
    dim3 gQKV(D_ / 128, M_ / 128, 3);   // (8, 64, 3)
    gemm_mma_kernel<<<gQKV, 256, GEMM_SMEM>>>(
        xb, wqb, wkb, wvb, bq, bk, bv, nullptr, Qb, Kb, Vb, nullptr, 1);

    dim3 gAttn(S_ / 128, B_ * H_);      // (8, 128)
    attn_kernel<<<gAttn, 256, ATTN_SMEM>>>(Qb, Kb, Vb, mask, ctxb);

    dim3 gO(D_ / 128, M_ / 128, 1);
    gemm_mma_kernel<<<gO, 256, GEMM_SMEM>>>(
        ctxb, wob, wob, wob, bo, bo, bo, x, nullptr, nullptr, nullptr, yp, 0);

    ln_kernel<<<M_, 256>>>(yp, gamma, beta, out);
}

// round 6
// speedup vs baseline: 6.9296x; 1.0411x over previous
#include <cuda_runtime.h>
#include <cuda_bf16.h>
#include <math.h>
#include <cstdint>

#define B_  8
#define S_  1024
#define H_  16
#define HD_ 64
#define D_  1024
#define M_  (B_ * S_)       // 8192
#define NINF_ (-10000.0f)

// ---------------- scratch (no allocs allowed) ----------------
__device__ __nv_bfloat16 g_xb[M_ * D_];
__device__ __nv_bfloat16 g_wqb[D_ * D_];   // native [K][N] layout, bf16
__device__ __nv_bfloat16 g_wkb[D_ * D_];
__device__ __nv_bfloat16 g_wvb[D_ * D_];
__device__ __nv_bfloat16 g_wob[D_ * D_];
__device__ __nv_bfloat16 g_Qb[M_ * D_];    // [B*H][S][HD]
__device__ __nv_bfloat16 g_Kb[M_ * D_];
__device__ __nv_bfloat16 g_Vb[M_ * D_];
__device__ __nv_bfloat16 g_ctxb[M_ * D_];  // [B*S][D]
__device__ float g_y[M_ * D_];

// ---------------- helpers ----------------
__device__ __forceinline__ uint32_t smem_u32(const void* p) {
    uint32_t a;
    asm("{ .reg .u64 t; cvta.to.shared.u64 t, %1; cvt.u32.u64 %0, t; }"
        : "=r"(a) : "l"(p));
    return a;
}
__device__ __forceinline__ void cpa16s(uint32_t s, const void* g) {
    asm volatile("cp.async.cg.shared.global [%0], [%1], 16;\n" :: "r"(s), "l"(g));
}
__device__ __forceinline__ void cp_commit() { asm volatile("cp.async.commit_group;\n"); }
__device__ __forceinline__ void cp_wait0()  { asm volatile("cp.async.wait_group 0;\n" ::: "memory"); }
__device__ __forceinline__ void cp_wait1()  { asm volatile("cp.async.wait_group 1;\n" ::: "memory"); }

__device__ __forceinline__ void ldmx4(uint32_t* r, uint32_t addr) {
    asm volatile("ldmatrix.sync.aligned.m8n8.x4.shared.b16 {%0,%1,%2,%3}, [%4];"
        : "=r"(r[0]), "=r"(r[1]), "=r"(r[2]), "=r"(r[3]) : "r"(addr));
}
__device__ __forceinline__ void ldmx4t(uint32_t* r, uint32_t addr) {
    asm volatile("ldmatrix.sync.aligned.m8n8.x4.trans.shared.b16 {%0,%1,%2,%3}, [%4];"
        : "=r"(r[0]), "=r"(r[1]), "=r"(r[2]), "=r"(r[3]) : "r"(addr));
}
__device__ __forceinline__ void mma16816(float* c, const uint32_t* a,
                                         uint32_t b0, uint32_t b1) {
    asm volatile("mma.sync.aligned.m16n8k16.row.col.f32.bf16.bf16.f32 "
        "{%0,%1,%2,%3}, {%4,%5,%6,%7}, {%8,%9}, {%0,%1,%2,%3};"
        : "+f"(c[0]), "+f"(c[1]), "+f"(c[2]), "+f"(c[3])
        : "r"(a[0]), "r"(a[1]), "r"(a[2]), "r"(a[3]), "r"(b0), "r"(b1));
}
__device__ __forceinline__ uint32_t packbf2(float lo, float hi) {
    __nv_bfloat162 t = __floats2bfloat162_rn(lo, hi);
    return *(uint32_t*)&t;
}

// ---------------------------------------------------------------------------
// One fused fp32->bf16 conversion for x + 4 weights.
// ---------------------------------------------------------------------------
#define XN (M_ * D_)          // 8388608
#define WN (D_ * D_)          // 1048576
__global__ __launch_bounds__(256) void cvt_all_kernel(
    const float* __restrict__ x,
    const float* __restrict__ wq, const float* __restrict__ wk,
    const float* __restrict__ wv, const float* __restrict__ wo,
    __nv_bfloat16* __restrict__ xb,
    __nv_bfloat16* __restrict__ wqb, __nv_bfloat16* __restrict__ wkb,
    __nv_bfloat16* __restrict__ wvb, __nv_bfloat16* __restrict__ wob)
{
    long long i = (long long)(blockIdx.x * 256 + threadIdx.x) * 4;
    const float* src;
    __nv_bfloat16* dst;
    long long off;
    if (i < XN)                { src = x;  dst = xb;  off = i; }
    else if (i < XN + WN)      { src = wq; dst = wqb; off = i - XN; }
    else if (i < XN + 2 * WN)  { src = wk; dst = wkb; off = i - XN - WN; }
    else if (i < XN + 3 * WN)  { src = wv; dst = wvb; off = i - XN - 2 * WN; }
    else                       { src = wo; dst = wob; off = i - XN - 3 * WN; }
    float4 v = *(const float4*)(src + off);
    *(__nv_bfloat162*)(dst + off)     = __floats2bfloat162_rn(v.x, v.y);
    *(__nv_bfloat162*)(dst + off + 2) = __floats2bfloat162_rn(v.z, v.w);
}

// ---------------------------------------------------------------------------
// mma.sync GEMM: C[8192,1024] = A[8192,1024] @ W[1024,1024] (W native [K][N])
// block 128x128, 8 warps 2(m)x4(n), warp 64x32, BK=64, 3-stage ring,
// ONE syncthreads per 64-wide K step (16 total).
// smem/stage: A 128x72 bf16 (18432B) + B 64x136 bf16 (17408B).
// ---------------------------------------------------------------------------
#define GAST 18432
#define GBST 17408
#define GBBASE (3 * GAST)
#define GEMM_SMEM (3 * GAST + 3 * GBST)   // 107520

__global__ __launch_bounds__(256, 2) void gemm_mma_kernel(
    const __nv_bfloat16* __restrict__ A,
    const __nv_bfloat16* __restrict__ W0, const __nv_bfloat16* __restrict__ W1,
    const __nv_bfloat16* __restrict__ W2,
    const float* __restrict__ b0p, const float* __restrict__ b1p,
    const float* __restrict__ b2p,
    const float* __restrict__ resid,
    __nv_bfloat16* __restrict__ O0, __nv_bfloat16* __restrict__ O1,
    __nv_bfloat16* __restrict__ O2,
    float* __restrict__ OutF, int heads_mode)
{
    extern __shared__ char smraw[];
    const uint32_t sb = smem_u32(smraw);
    const int tid = threadIdx.x;
    const int wid = tid >> 5, lane = tid & 31;
    const int wm = wid >> 2, wn = wid & 3;
    const int bm = blockIdx.y * 128, bn = blockIdx.x * 128;
    const int z = blockIdx.z;

    const __nv_bfloat16* W = (z == 0) ? W0 : (z == 1) ? W1 : W2;
    const float* bias       = (z == 0) ? b0p : (z == 1) ? b1p : b2p;
    __nv_bfloat16* OutB     = (z == 0) ? O0 : (z == 1) ? O1 : O2;

    const __nv_bfloat16* Ag = A + (size_t)bm * D_;
    const __nv_bfloat16* Wg = W + bn;

    float acc[16][4];
#pragma unroll
    for (int i = 0; i < 16; i++)
#pragma unroll
        for (int j = 0; j < 4; j++) acc[i][j] = 0.f;

    // per-K-step (64 wide) load: A 128x64 halves, B 64x128 halves
#define GLOAD(u, st) do { \
        const uint32_t as = sb + (st) * GAST; \
        const uint32_t bs = sb + GBBASE + (st) * GBST; \
        const __nv_bfloat16* ap = Ag + (u) * 64; \
        const __nv_bfloat16* wp = Wg + (size_t)((u) * 64) * D_; \
        _Pragma("unroll") \
        for (int i = 0; i < 4; i++) { \
            int idx = i * 256 + tid; \
            int ra = idx >> 3, ca = (idx & 7) * 8; \
            cpa16s(as + (uint32_t)(ra * 72 + ca) * 2, ap + (size_t)ra * D_ + ca); \
            int rb = idx >> 4, cb = (idx & 15) * 8; \
            cpa16s(bs + (uint32_t)(rb * 136 + cb) * 2, wp + (size_t)rb * D_ + cb); \
        } \
    } while (0)

    GLOAD(0, 0); cp_commit();
    GLOAD(1, 1); cp_commit();

    int sr = 0, sw = 2;
    for (int u = 0; u < 16; u++) {
        cp_wait1();
        __syncthreads();
        if (u + 2 < 16) GLOAD(u + 2, sw);
        cp_commit();

        const uint32_t as = sb + sr * GAST;
        const uint32_t bs = sb + GBBASE + sr * GBST;
#pragma unroll
        for (int kk = 0; kk < 4; kk++) {
            uint32_t a[4][4];
#pragma unroll
            for (int i = 0; i < 4; i++) {
                int row = wm * 64 + i * 16 + (lane & 7) + ((lane >> 3) & 1) * 8;
                int col = kk * 16 + (lane >> 4) * 8;
                ldmx4(a[i], as + (uint32_t)(row * 72 + col) * 2);
            }
#pragma unroll
            for (int jp = 0; jp < 2; jp++) {
                int row = kk * 16 + (lane & 7) + ((lane >> 3) & 1) * 8;
                int col = wn * 32 + jp * 16 + (lane >> 4) * 8;
                uint32_t r4[4];
                ldmx4t(r4, bs + (uint32_t)(row * 136 + col) * 2);
#pragma unroll
                for (int i = 0; i < 4; i++) {
                    mma16816(acc[i * 4 + jp * 2],     a[i], r4[0], r4[1]);
                    mma16816(acc[i * 4 + jp * 2 + 1], a[i], r4[2], r4[3]);
                }
            }
        }
        sr = (sr == 2) ? 0 : sr + 1;
        sw = (sw == 2) ? 0 : sw + 1;
    }
#undef GLOAD

    // epilogue: direct from registers
#pragma unroll
    for (int i = 0; i < 4; i++) {
        const int m0 = bm + wm * 64 + i * 16 + (lane >> 2);
#pragma unroll
        for (int j = 0; j < 4; j++) {
            const int n = bn + wn * 32 + j * 8 + 2 * (lane & 3);
            const float2 bb = *(const float2*)(bias + n);
            float v0 = acc[i * 4 + j][0] + bb.x;
            float v1 = acc[i * 4 + j][1] + bb.y;
            float v2 = acc[i * 4 + j][2] + bb.x;
            float v3 = acc[i * 4 + j][3] + bb.y;
            if (heads_mode) {
                const int h = n >> 6, hd = n & 63;
                {
                    int b = m0 >> 10, s = m0 & 1023;
                    *(__nv_bfloat162*)(OutB + (((size_t)((b << 4) + h)) << 16)
                                       + ((size_t)s << 6) + hd)
                        = __floats2bfloat162_rn(v0, v1);
                }
                {
                    int m1 = m0 + 8;
                    int b = m1 >> 10, s = m1 & 1023;
                    *(__nv_bfloat162*)(OutB + (((size_t)((b << 4) + h)) << 16)
                                       + ((size_t)s << 6) + hd)
                        = __floats2bfloat162_rn(v2, v3);
                }
            } else {
                size_t off0 = (size_t)m0 * D_ + n;
                size_t off1 = (size_t)(m0 + 8) * D_ + n;
                float2 r0 = *(const float2*)(resid + off0);
                float2 r1 = *(const float2*)(resid + off1);
                *(float2*)(OutF + off0) = make_float2(v0 + r0.x, v1 + r0.y);
                *(float2*)(OutF + off1) = make_float2(v2 + r1.x, v3 + r1.y);
            }
        }
    }
}

// ---------------------------------------------------------------------------
// Attention, mma.sync. Block = (b,h) x 128 q rows. 8 warps, warp = 16 q rows.
// Scores computed in two 64-key halves (cuts regs -> 2 CTAs/SM).
// ---------------------------------------------------------------------------
#define AQOFF 0
#define AKOFF 18432
#define AVOFF (18432 + 36864)
#define AMOFF 92160
#define ATTN_SMEM (92160 + 1024)

__global__ __launch_bounds__(256, 2) void attn_kernel(
    const __nv_bfloat16* __restrict__ Q, const __nv_bfloat16* __restrict__ K,
    const __nv_bfloat16* __restrict__ V, const int* __restrict__ mask,
    __nv_bfloat16* __restrict__ ctx)
{
    extern __shared__ char smraw[];
    const uint32_t sb = smem_u32(smraw);
    const int tid = threadIdx.x;
    const int wid = tid >> 5, lane = tid & 31;
    const int bh = blockIdx.y;
    const int b = bh >> 4, h = bh & 15;
    const int q0 = blockIdx.x * 128;

    const __nv_bfloat16* Qp = Q + (((size_t)bh) << 16) + (size_t)q0 * HD_;
    const __nv_bfloat16* Kp = K + (((size_t)bh) << 16);
    const __nv_bfloat16* Vp = V + (((size_t)bh) << 16);
    const int* mp = mask + b * S_;

#pragma unroll
    for (int i = 0; i < 4; i++) {
        int idx = i * 256 + tid;
        int r = idx >> 3, c = (idx & 7) * 8;
        cpa16s(sb + AQOFF + (uint32_t)(r * 72 + c) * 2, Qp + (size_t)r * HD_ + c);
    }
#define LOADKV(it, buf) do { \
        const int k0 = (it) * 128; \
        _Pragma("unroll") \
        for (int i = 0; i < 4; i++) { \
            int idx = i * 256 + tid; int r = idx >> 3, c = (idx & 7) * 8; \
            cpa16s(sb + AKOFF + (buf) * 18432 + (uint32_t)(r * 72 + c) * 2, \
                   Kp + (size_t)(k0 + r) * HD_ + c); \
            cpa16s(sb + AVOFF + (buf) * 18432 + (uint32_t)(r * 72 + c) * 2, \
                   Vp + (size_t)(k0 + r) * HD_ + c); \
        } \
        if (tid < 32) cpa16s(sb + AMOFF + (buf) * 512 + tid * 16, mp + k0 + tid * 4); \
    } while (0)

    LOADKV(0, 0);
    cp_commit();

    uint32_t qf[4][4];
    float oacc[8][4];
#pragma unroll
    for (int i = 0; i < 8; i++)
#pragma unroll
        for (int j = 0; j < 4; j++) oacc[i][j] = 0.f;
    float lsum0 = 0.f, lsum1 = 0.f;

    for (int it = 0; it < 8; it++) {
        cp_wait0();
        __syncthreads();
        if (it + 1 < 8) LOADKV(it + 1, (it + 1) & 1);
        cp_commit();

        if (it == 0) {
#pragma unroll
            for (int kk = 0; kk < 4; kk++) {
                int row = wid * 16 + (lane & 7) + ((lane >> 3) & 1) * 8;
                int col = kk * 16 + (lane >> 4) * 8;
                ldmx4(qf[kk], sb + AQOFF + (uint32_t)(row * 72 + col) * 2);
            }
        }

        const int buf = it & 1;
        const uint32_t ksb = sb + AKOFF + buf * 18432;
        const uint32_t vsb = sb + AVOFF + buf * 18432;
        const int* msk = (const int*)(smraw + AMOFF + buf * 512);

        // two 64-key halves: scores -> softmax -> PV per half
#pragma unroll
        for (int half = 0; half < 2; half++) {
            float sacc[8][4];
#pragma unroll
            for (int i = 0; i < 8; i++)
#pragma unroll
                for (int j = 0; j < 4; j++) sacc[i][j] = 0.f;

#pragma unroll
            for (int kk = 0; kk < 4; kk++) {
#pragma unroll
                for (int jp = 0; jp < 4; jp++) {
                    int row = half * 64 + jp * 16 + (lane & 7) + ((lane >> 3) & 1) * 8;
                    int col = kk * 16 + (lane >> 4) * 8;
                    uint32_t r4[4];
                    ldmx4(r4, ksb + (uint32_t)(row * 72 + col) * 2);
                    mma16816(sacc[jp * 2],     qf[kk], r4[0], r4[2]);
                    mma16816(sacc[jp * 2 + 1], qf[kk], r4[1], r4[3]);
                }
            }

            uint32_t pf[4][4];
#pragma unroll
            for (int j = 0; j < 8; j++) {
                const int n0 = half * 64 + j * 8 + 2 * (lane & 3);
                const float mk0 = NINF_ * (float)msk[n0];
                const float mk1 = NINF_ * (float)msk[n0 + 1];
                float e0 = __expf(fmaf(sacc[j][0], 0.125f, mk0));
                float e1 = __expf(fmaf(sacc[j][1], 0.125f, mk1));
                float e2 = __expf(fmaf(sacc[j][2], 0.125f, mk0));
                float e3 = __expf(fmaf(sacc[j][3], 0.125f, mk1));
                lsum0 += e0 + e1;
                lsum1 += e2 + e3;
                const int kk2 = j >> 1;
                if ((j & 1) == 0) {
                    pf[kk2][0] = packbf2(e0, e1);
                    pf[kk2][1] = packbf2(e2, e3);
                } else {
                    pf[kk2][2] = packbf2(e0, e1);
                    pf[kk2][3] = packbf2(e2, e3);
                }
            }

#pragma unroll
            for (int kk2 = 0; kk2 < 4; kk2++) {
#pragma unroll
                for (int jp = 0; jp < 4; jp++) {
                    int row = half * 64 + kk2 * 16 + (lane & 7) + ((lane >> 3) & 1) * 8;
                    int col = jp * 16 + (lane >> 4) * 8;
                    uint32_t r4[4];
                    ldmx4t(r4, vsb + (uint32_t)(row * 72 + col) * 2);
                    mma16816(oacc[jp * 2],     pf[kk2], r4[0], r4[1]);
                    mma16816(oacc[jp * 2 + 1], pf[kk2], r4[2], r4[3]);
                }
            }
        }
    }
#undef LOADKV

    lsum0 += __shfl_xor_sync(0xffffffffu, lsum0, 1);
    lsum0 += __shfl_xor_sync(0xffffffffu, lsum0, 2);
    lsum1 += __shfl_xor_sync(0xffffffffu, lsum1, 1);
    lsum1 += __shfl_xor_sync(0xffffffffu, lsum1, 2);
    const float inv0 = 1.0f / lsum0;
    const float inv1 = 1.0f / lsum1;

    const int row0 = q0 + wid * 16 + (lane >> 2);
#pragma unroll
    for (int j2 = 0; j2 < 8; j2++) {
        const int col = h * HD_ + j2 * 8 + 2 * (lane & 3);
        size_t off0 = (size_t)(b * S_ + row0) * D_ + col;
        size_t off1 = (size_t)(b * S_ + row0 + 8) * D_ + col;
        *(__nv_bfloat162*)(ctx + off0) =
            __floats2bfloat162_rn(oacc[j2][0] * inv0, oacc[j2][1] * inv0);
        *(__nv_bfloat162*)(ctx + off1) =
            __floats2bfloat162_rn(oacc[j2][2] * inv1, oacc[j2][3] * inv1);
    }
}

// ---------------------------------------------------------------------------
// Row LayerNorm over [M, 1024]
// ---------------------------------------------------------------------------
__global__ __launch_bounds__(256) void ln_kernel(
    const float* __restrict__ Y, const float* __restrict__ gamma,
    const float* __restrict__ beta, float* __restrict__ O)
{
    __shared__ float red[16];
    const int row = blockIdx.x;
    const int t = threadIdx.x;
    const float* yr = Y + (size_t)row * D_;
    float4 v = *(const float4*)(yr + t * 4);
    float s  = v.x + v.y + v.z + v.w;
    float sq = v.x * v.x + v.y * v.y + v.z * v.z + v.w * v.w;
#pragma unroll
    for (int o = 16; o; o >>= 1) {
        s  += __shfl_xor_sync(0xffffffffu, s, o);
        sq += __shfl_xor_sync(0xffffffffu, sq, o);
    }
    int w = t >> 5;
    if ((t & 31) == 0) { red[w] = s; red[8 + w] = sq; }
    __syncthreads();
    if (t < 32) {
        s  = (t < 8) ? red[t] : 0.f;
        sq = (t < 8) ? red[8 + t] : 0.f;
#pragma unroll
        for (int o = 4; o; o >>= 1) {
            s  += __shfl_xor_sync(0xffffffffu, s, o);
            sq += __shfl_xor_sync(0xffffffffu, sq, o);
        }
        if (t == 0) { red[0] = s; red[1] = sq; }
    }
    __syncthreads();
    float mu  = red[0] * (1.0f / D_);
    float var = red[1] * (1.0f / D_) - mu * mu;
    float rstd = rsqrtf(var + 1e-6f);
    float4 g  = *(const float4*)(gamma + t * 4);
    float4 be = *(const float4*)(beta + t * 4);
    float4 o;
    o.x = (v.x - mu) * rstd * g.x + be.x;
    o.y = (v.y - mu) * rstd * g.y + be.y;
    o.z = (v.z - mu) * rstd * g.z + be.z;
    o.w = (v.w - mu) * rstd * g.w + be.w;
    *(float4*)(O + (size_t)row * D_ + t * 4) = o;
}

// ---------------------------------------------------------------------------
// Launch
// ---------------------------------------------------------------------------
extern "C" void kernel_launch(void* const* d_in, const int* in_sizes, int n_in,
                              void* d_out, int out_size)
{
    const float* x     = (const float*)d_in[0];
    const int*   mask  = (const int*)d_in[1];
    const float* wq    = (const float*)d_in[2];
    const float* bq    = (const float*)d_in[3];
    const float* wk    = (const float*)d_in[4];
    const float* bk    = (const float*)d_in[5];
    const float* wv    = (const float*)d_in[6];
    const float* bv    = (const float*)d_in[7];
    const float* wo    = (const float*)d_in[8];
    const float* bo    = (const float*)d_in[9];
    const float* gamma = (const float*)d_in[10];
    const float* beta  = (const float*)d_in[11];
    float* out = (float*)d_out;

    __nv_bfloat16 *xb, *wqb, *wkb, *wvb, *wob, *Qb, *Kb, *Vb, *ctxb;
    float* yp;
    cudaGetSymbolAddress((void**)&xb,  g_xb);
    cudaGetSymbolAddress((void**)&wqb, g_wqb);
    cudaGetSymbolAddress((void**)&wkb, g_wkb);
    cudaGetSymbolAddress((void**)&wvb, g_wvb);
    cudaGetSymbolAddress((void**)&wob, g_wob);
    cudaGetSymbolAddress((void**)&Qb,  g_Qb);
    cudaGetSymbolAddress((void**)&Kb,  g_Kb);
    cudaGetSymbolAddress((void**)&Vb,  g_Vb);
    cudaGetSymbolAddress((void**)&ctxb, g_ctxb);
    cudaGetSymbolAddress((void**)&yp,  g_y);

    cudaFuncSetAttribute(gemm_mma_kernel,
                         cudaFuncAttributeMaxDynamicSharedMemorySize, GEMM_SMEM);
    cudaFuncSetAttribute(attn_kernel,
                         cudaFuncAttributeMaxDynamicSharedMemorySize, ATTN_SMEM);

    cvt_all_kernel<<<(XN + 4 * WN) / 1024, 256>>>(
        x, wq, wk, wv, wo, xb, wqb, wkb, wvb, wob);

    dim3 gQKV(D_ / 128, M_ / 128, 3);   // (8, 64, 3)
    gemm_mma_kernel<<<gQKV, 256, GEMM_SMEM>>>(
        xb, wqb, wkb, wvb, bq, bk, bv, nullptr, Qb, Kb, Vb, nullptr, 1);

    dim3 gAttn(S_ / 128, B_ * H_);      // (8, 128)
    attn_kernel<<<gAttn, 256, ATTN_SMEM>>>(Qb, Kb, Vb, mask, ctxb);

    dim3 gO(D_ / 128, M_ / 128, 1);
    gemm_mma_kernel<<<gO, 256, GEMM_SMEM>>>(
        ctxb, wob, wob, wob, bo, bo, bo, x, nullptr, nullptr, nullptr, yp, 0);

    ln_kernel<<<M_, 256>>>(yp, gamma, beta, out);
}